// round 9
// baseline (speedup 1.0000x reference)
#include <cuda_runtime.h>
#include <math.h>

#define NIMG 512
#define NCLS 100000

// ---------------- packed f32x2 helpers (sm_103a FFMA2) ----------------
__device__ __forceinline__ long long pack2(float x, float y) {
    long long r;
    asm("mov.b64 %0, {%1, %2};" : "=l"(r) : "f"(x), "f"(y));
    return r;
}
__device__ __forceinline__ void unpack2(long long p, float& x, float& y) {
    asm("mov.b64 {%0, %1}, %2;" : "=f"(x), "=f"(y) : "l"(p));
}
__device__ __forceinline__ void ffma2(long long& d, long long a, long long b) {
    asm("fma.rn.f32x2 %0, %1, %2, %0;" : "+l"(d) : "l"(a), "l"(b));
}

// ---------------- scratch (device globals; no allocation) ----------------
__device__ float g_y1[512 * 16 * 56 * 56];   // conv1 raw out
__device__ float g_y2[512 * 32 * 28 * 28];   // conv2 raw out
__device__ float g_y3[512 * 64 * 26 * 26];   // conv3 raw out
__device__ float g_y4[512 * 128 * 24 * 24];  // conv4 raw out
__device__ float g_f[512 * 128];
__device__ float g_fn[512 * 128];
__device__ float g_wn[NCLS * 128];
__device__ float g_s1[16], g_q1[16], g_sc1[16], g_sh1[16];
__device__ float g_s2[32], g_q2[32], g_sc2[32], g_sh2[32];
__device__ float g_s3[64], g_q3[64], g_sc3[64], g_sh3[64];
__device__ float g_s4[128], g_q4[128], g_sc4[128], g_sh4[128];

__global__ void zero_stats_k() {
    int t = threadIdx.x;
    if (t < 16)  { g_s1[t] = 0.f; g_q1[t] = 0.f; }
    if (t < 32)  { g_s2[t] = 0.f; g_q2[t] = 0.f; }
    if (t < 64)  { g_s3[t] = 0.f; g_q3[t] = 0.f; }
    if (t < 128) { g_s4[t] = 0.f; g_q4[t] = 0.f; }
}

// stats -> (scale, shift)
__global__ void scale_k(const float* __restrict__ s, const float* __restrict__ q,
                        const float* __restrict__ g, const float* __restrict__ be,
                        float* __restrict__ sc, float* __restrict__ sh, int C, float invCnt) {
    int c = threadIdx.x;
    if (c >= C) return;
    float mu = s[c] * invCnt;
    float var = fmaxf(q[c] * invCnt - mu * mu, 0.f);
    float a = g[c] * rsqrtf(var + 1e-5f);
    sc[c] = a;
    sh[c] = be[c] - mu * a;
}

// ---------------- conv1: 1->16, 4x4, s2, p1, 112 -> 56 (+fused stats) ----------------
__global__ __launch_bounds__(256) void conv1_k(const float* __restrict__ x,
                                               const float* __restrict__ w) {
    __shared__ float ws[256];  // [tap][oc]
    __shared__ float bs[16], bq[16];
    int tid = threadIdx.x;
    ws[(tid & 15) * 16 + (tid >> 4)] = w[tid];
    if (tid < 16) { bs[tid] = 0.f; bq[tid] = 0.f; }
    __syncthreads();
    int n = blockIdx.x;
    int p = blockIdx.y * 256 + tid;
    bool valid = (p < 3136);
    int pc = valid ? p : 3135;
    int oh = pc / 56, ow = pc % 56;
    const float* xin = x + (size_t)n * 112 * 112;
    float acc[16];
#pragma unroll
    for (int i = 0; i < 16; i++) acc[i] = 0.f;
#pragma unroll
    for (int kh = 0; kh < 4; kh++) {
        int ih = oh * 2 - 1 + kh;
        bool vh = ((unsigned)ih < 112u);
#pragma unroll
        for (int kw = 0; kw < 4; kw++) {
            int iw = ow * 2 - 1 + kw;
            float v = (vh && ((unsigned)iw < 112u)) ? xin[ih * 112 + iw] : 0.f;
            const float4* wp = (const float4*)(ws + (kh * 4 + kw) * 16);
#pragma unroll
            for (int q = 0; q < 4; q++) {
                float4 wv = wp[q];
                acc[4 * q + 0] += v * wv.x;
                acc[4 * q + 1] += v * wv.y;
                acc[4 * q + 2] += v * wv.z;
                acc[4 * q + 3] += v * wv.w;
            }
        }
    }
    float* out = g_y1 + (size_t)n * 16 * 3136;
    if (valid) {
#pragma unroll
        for (int oc = 0; oc < 16; oc++) out[oc * 3136 + p] = acc[oc];
    }
    int lane = tid & 31;
#pragma unroll
    for (int oc = 0; oc < 16; oc++) {
        float v = valid ? acc[oc] : 0.f;
        float q = v * v;
#pragma unroll
        for (int o = 16; o > 0; o >>= 1) {
            v += __shfl_xor_sync(0xffffffffu, v, o);
            q += __shfl_xor_sync(0xffffffffu, q, o);
        }
        if (lane == 0) { atomicAdd(&bs[oc], v); atomicAdd(&bq[oc], q); }
    }
    __syncthreads();
    if (tid < 16) { atomicAdd(&g_s1[tid], bs[tid]); atomicAdd(&g_q1[tid], bq[tid]); }
}

// ---------------- conv2: 16->32, 4x4, s2, p1, 56 -> 28 ----------------
// 16 OCs per block (blockIdx.y), packed f32x2 accumulators over adjacent pixel pairs.
__global__ __launch_bounds__(416, 2) void conv2_k(const float* __restrict__ w) {
    __shared__ float smi[2 * 58 * 58];
    __shared__ __align__(16) float2 smwd[2 * 16 * 16];  // [icl][tap][oc] duplicated
    __shared__ float bs[16], bq[16];
    const int tid = threadIdx.x;
    const int n = blockIdx.x;
    const int ocb = blockIdx.y;  // 0 or 1

    for (int i = tid; i < 2 * 58 * 58; i += 416) smi[i] = 0.f;
    if (tid < 16) { bs[tid] = 0.f; bq[tid] = 0.f; }

    const int p0 = 2 * tid;  // adjacent pixel pair (p0, p0+1), same row (28 even)
    const bool pv = (p0 < 784);
    const int pc = pv ? p0 : 0;
    const int oh = pc / 28, ow = pc % 28;

    long long acc[16];
#pragma unroll
    for (int i = 0; i < 16; i++) acc[i] = 0;

    const float* ain = g_y1 + (size_t)n * 16 * 3136;
    __syncthreads();

#pragma unroll 1
    for (int ic0 = 0; ic0 < 16; ic0 += 2) {
        float scA = g_sc1[ic0], shA = g_sh1[ic0];
        float scB = g_sc1[ic0 + 1], shB = g_sh1[ic0 + 1];
        for (int i = tid; i < 2 * 3136; i += 416) {
            int icl = i / 3136, r = i % 3136;
            int ih = r / 56, iw = r % 56;
            float raw = ain[(ic0 + icl) * 3136 + r];
            float sc = icl ? scB : scA, sh = icl ? shB : shA;
            smi[icl * 3364 + (ih + 1) * 58 + (iw + 1)] = fmaxf(fmaf(raw, sc, sh), 0.f);
        }
        for (int i = tid; i < 512; i += 416) {
            int oc = i & 15, t = (i >> 4) & 15, icl = i >> 8;
            float wv = w[((ocb * 16 + oc) * 16 + (ic0 + icl)) * 16 + t];
            smwd[(icl * 16 + t) * 16 + oc] = make_float2(wv, wv);
        }
        __syncthreads();
#pragma unroll 1
        for (int icl = 0; icl < 2; icl++) {
            const float* sip = smi + icl * 3364;
#pragma unroll
            for (int t = 0; t < 16; t++) {
                int kh = t >> 2, kw = t & 3;
                const float* rp = sip + (oh * 2 + kh) * 58 + ow * 2 + kw;
                long long inp = pack2(rp[0], rp[2]);  // stride-2 conv: inputs 2 apart
                const longlong2* wp = (const longlong2*)(smwd + (icl * 16 + t) * 16);
#pragma unroll
                for (int q = 0; q < 8; q++) {
                    longlong2 wv = wp[q];
                    ffma2(acc[2 * q + 0], inp, wv.x);
                    ffma2(acc[2 * q + 1], inp, wv.y);
                }
            }
        }
        __syncthreads();
    }
    float* out = g_y2 + ((size_t)n * 32 + ocb * 16) * 784;
    int lane = tid & 31;
#pragma unroll
    for (int oc = 0; oc < 16; oc++) {
        float a0, a1;
        unpack2(acc[oc], a0, a1);
        if (pv) *(float2*)(out + oc * 784 + p0) = make_float2(a0, a1);
        float v = pv ? (a0 + a1) : 0.f;
        float q = pv ? (a0 * a0 + a1 * a1) : 0.f;
#pragma unroll
        for (int o = 16; o > 0; o >>= 1) {
            v += __shfl_xor_sync(0xffffffffu, v, o);
            q += __shfl_xor_sync(0xffffffffu, q, o);
        }
        if (lane == 0) { atomicAdd(&bs[oc], v); atomicAdd(&bq[oc], q); }
    }
    __syncthreads();
    if (tid < 16) { atomicAdd(&g_s2[ocb * 16 + tid], bs[tid]); atomicAdd(&g_q2[ocb * 16 + tid], bq[tid]); }
}

// ---------------- generic 3x3 s1 p0 conv, 16 OCs/block, packed f32x2, bn+relu in, stats out ----
template <int IC, int OC, int IH, int OW, int THREADS>
__global__ __launch_bounds__(THREADS, 2) void conv3x3_k(
    const float* __restrict__ act, const float* __restrict__ w, float* __restrict__ out,
    const float* __restrict__ isc, const float* __restrict__ ish,
    float* __restrict__ gs, float* __restrict__ gq) {
    constexpr int IHW = IH * IH;
    constexpr int PIX = OW * OW;
    __shared__ float smi[8 * IHW];
    __shared__ __align__(16) float2 smwd[8 * 9 * 16];  // [icl][tap][oc] duplicated
    __shared__ float bs[16], bq[16];
    const int tid = threadIdx.x;
    const int n = blockIdx.x;
    const int ocb = blockIdx.y;

    if (tid < 16) { bs[tid] = 0.f; bq[tid] = 0.f; }

    const int p0 = 2 * tid;  // adjacent pixel pair; OW even -> same output row
    const bool pv = (p0 < PIX);
    const int pc = pv ? p0 : 0;
    const int oh = pc / OW, ow = pc % OW;

    long long acc[16];
#pragma unroll
    for (int i = 0; i < 16; i++) acc[i] = 0;

    const float* ain = act + (size_t)n * IC * IHW;

#pragma unroll 1
    for (int ic0 = 0; ic0 < IC; ic0 += 8) {
        for (int i = tid; i < 8 * IHW; i += THREADS) {
            int c = ic0 + i / IHW;
            smi[i] = fmaxf(fmaf(ain[ic0 * IHW + i], __ldg(&isc[c]), __ldg(&ish[c])), 0.f);
        }
        for (int i = tid; i < 8 * 9 * 16; i += THREADS) {
            int oc = i & 15;
            int t = (i >> 4) % 9;
            int icl = i / 144;
            float wv = w[(((ocb * 16 + oc) * IC) + ic0 + icl) * 9 + t];
            smwd[(icl * 9 + t) * 16 + oc] = make_float2(wv, wv);
        }
        __syncthreads();
#pragma unroll 1
        for (int icl = 0; icl < 8; icl++) {
            const float* sip = smi + icl * IHW;
#pragma unroll
            for (int t = 0; t < 9; t++) {
                int kh = t / 3, kw = t % 3;
                const float* rp = sip + (oh + kh) * IH + ow + kw;
                long long inp = pack2(rp[0], rp[1]);
                const longlong2* wp = (const longlong2*)(smwd + (icl * 9 + t) * 16);
#pragma unroll
                for (int q = 0; q < 8; q++) {
                    longlong2 wv = wp[q];
                    ffma2(acc[2 * q + 0], inp, wv.x);
                    ffma2(acc[2 * q + 1], inp, wv.y);
                }
            }
        }
        __syncthreads();
    }

    float* op = out + ((size_t)n * OC + ocb * 16) * PIX;
    int lane = tid & 31;
#pragma unroll
    for (int oc = 0; oc < 16; oc++) {
        float a0, a1;
        unpack2(acc[oc], a0, a1);
        if (pv) *(float2*)(op + oc * PIX + p0) = make_float2(a0, a1);
        float v = pv ? (a0 + a1) : 0.f;
        float q = pv ? (a0 * a0 + a1 * a1) : 0.f;
#pragma unroll
        for (int o = 16; o > 0; o >>= 1) {
            v += __shfl_xor_sync(0xffffffffu, v, o);
            q += __shfl_xor_sync(0xffffffffu, q, o);
        }
        if (lane == 0) { atomicAdd(&bs[oc], v); atomicAdd(&bq[oc], q); }
    }
    __syncthreads();
    if (tid < 16) {
        atomicAdd(&gs[ocb * 16 + tid], bs[tid]);
        atomicAdd(&gq[ocb * 16 + tid], bq[tid]);
    }
}

// ---------------- GAP with bn4+relu fused: (512,128,24,24) -> (512,128) ----------------
__global__ void gap_k() {
    int pair = blockIdx.x * 8 + (threadIdx.x >> 5);
    int c = pair & 127;
    int lane = threadIdx.x & 31;
    float sc = g_sc4[c], sh = g_sh4[c];
    const float* p = g_y4 + (size_t)pair * 576;
    float s = 0.f;
    for (int i = lane; i < 576; i += 32) s += fmaxf(fmaf(p[i], sc, sh), 0.f);
#pragma unroll
    for (int o = 16; o > 0; o >>= 1) s += __shfl_xor_sync(0xffffffffu, s, o);
    if (lane == 0) g_f[pair] = s * (1.f / 576.f);
}

// ---------------- row-wise L2 normalize (K = 128) ----------------
__global__ void l2norm_body_k(const float* __restrict__ in, float* __restrict__ out, int rows) {
    int r = blockIdx.x * 8 + (threadIdx.x >> 5);
    if (r >= rows) return;
    int lane = threadIdx.x & 31;
    const float* p = in + (size_t)r * 128;
    float v0 = p[lane], v1 = p[lane + 32], v2 = p[lane + 64], v3 = p[lane + 96];
    float sq = v0 * v0 + v1 * v1 + v2 * v2 + v3 * v3;
#pragma unroll
    for (int o = 16; o > 0; o >>= 1) sq += __shfl_xor_sync(0xffffffffu, sq, o);
    float inv = 1.f / fmaxf(sqrtf(sq), 1e-12f);
    float* op = out + (size_t)r * 128;
    op[lane] = v0 * inv;
    op[lane + 32] = v1 * inv;
    op[lane + 64] = v2 * inv;
    op[lane + 96] = v3 * inv;
}

// ---------------- SGEMM: (512 x 128) @ (128 x 100000)^T, x64 scale ----------------
__global__ __launch_bounds__(256) void sgemm_k(const float* __restrict__ A,
                                               const float* __restrict__ B,
                                               float* __restrict__ C) {
    __shared__ float As[8][128];
    __shared__ float Bs[8][128];
    const int tid = threadIdx.x;
    const int bm = blockIdx.y * 128;
    const int bn = blockIdx.x * 128;
    const int tm = (tid >> 4) << 3;
    const int tn = (tid & 15) << 3;

    float acc[8][8];
#pragma unroll
    for (int i = 0; i < 8; i++)
#pragma unroll
        for (int j = 0; j < 8; j++) acc[i][j] = 0.f;

    const int lr = tid >> 1;
    const int lk = (tid & 1) << 2;
    const float* Ag = A + (size_t)(bm + lr) * 128 + lk;
    const int brow = bn + lr;
    const float* Bg = B + (size_t)brow * 128 + lk;
    const bool bvalid = (brow < NCLS);

#pragma unroll 1
    for (int k0 = 0; k0 < 128; k0 += 8) {
        float4 av = *(const float4*)(Ag + k0);
        float4 bv = bvalid ? *(const float4*)(Bg + k0) : make_float4(0.f, 0.f, 0.f, 0.f);
        As[lk + 0][lr] = av.x; As[lk + 1][lr] = av.y; As[lk + 2][lr] = av.z; As[lk + 3][lr] = av.w;
        Bs[lk + 0][lr] = bv.x; Bs[lk + 1][lr] = bv.y; Bs[lk + 2][lr] = bv.z; Bs[lk + 3][lr] = bv.w;
        __syncthreads();
#pragma unroll
        for (int kk = 0; kk < 8; kk++) {
            float a[8], b[8];
            *(float4*)(a) = *(const float4*)&As[kk][tm];
            *(float4*)(a + 4) = *(const float4*)&As[kk][tm + 4];
            *(float4*)(b) = *(const float4*)&Bs[kk][tn];
            *(float4*)(b + 4) = *(const float4*)&Bs[kk][tn + 4];
#pragma unroll
            for (int i = 0; i < 8; i++)
#pragma unroll
                for (int j = 0; j < 8; j++) acc[i][j] += a[i] * b[j];
        }
        __syncthreads();
    }

    const bool full = (bn + 128 <= NCLS);
#pragma unroll
    for (int i = 0; i < 8; i++) {
        float* cp = C + (size_t)(bm + tm + i) * NCLS + bn + tn;
        if (full) {
            float4 o0 = make_float4(64.f * acc[i][0], 64.f * acc[i][1],
                                    64.f * acc[i][2], 64.f * acc[i][3]);
            float4 o1 = make_float4(64.f * acc[i][4], 64.f * acc[i][5],
                                    64.f * acc[i][6], 64.f * acc[i][7]);
            *(float4*)cp = o0;
            *(float4*)(cp + 4) = o1;
        } else {
#pragma unroll
            for (int j = 0; j < 8; j++)
                if (bn + tn + j < NCLS) cp[j] = 64.f * acc[i][j];
        }
    }
}

// ---------------- ArcFace margin fix-up ----------------
__global__ void margin_k(const int* __restrict__ gt, float* __restrict__ out) {
    int n = blockIdx.x * 256 + threadIdx.x;
    if (n >= NIMG) return;
    int c = gt[n];
    size_t idx = (size_t)n * NCLS + c;
    float v = out[idx] * (1.f / 64.f);
    float s = sqrtf(fmaxf(1.f - v * v, 0.f));
    const float cm = 0.87758256189037271612f;  // cos(0.5)
    const float sm = 0.47942553860420300027f;  // sin(0.5)
    out[idx] = 64.f * (v * cm - s * sm);
}

// ---------------- launch ----------------
extern "C" void kernel_launch(void* const* d_in, const int* in_sizes, int n_in,
                              void* d_out, int out_size) {
    const float* x  = (const float*)d_in[0];
    const int*   gt = (const int*)d_in[1];
    const float* w1 = (const float*)d_in[2];
    const float* g1 = (const float*)d_in[4];
    const float* be1 = (const float*)d_in[5];
    const float* w2 = (const float*)d_in[6];
    const float* g2 = (const float*)d_in[8];
    const float* be2 = (const float*)d_in[9];
    const float* w3 = (const float*)d_in[10];
    const float* g3 = (const float*)d_in[12];
    const float* be3 = (const float*)d_in[13];
    const float* w4 = (const float*)d_in[14];
    const float* g4 = (const float*)d_in[16];
    const float* be4 = (const float*)d_in[17];
    const float* aw = (const float*)d_in[18];
    float* out = (float*)d_out;

    // Resolve REAL device addresses of __device__ globals.
    float *p_y2, *p_y3, *p_y4, *p_f, *p_fn, *p_wn;
    float *p_s1, *p_q1, *p_sc1, *p_sh1;
    float *p_s2, *p_q2, *p_sc2, *p_sh2;
    float *p_s3, *p_q3, *p_sc3, *p_sh3;
    float *p_s4, *p_q4, *p_sc4, *p_sh4;
    cudaGetSymbolAddress((void**)&p_y2, g_y2);
    cudaGetSymbolAddress((void**)&p_y3, g_y3);
    cudaGetSymbolAddress((void**)&p_y4, g_y4);
    cudaGetSymbolAddress((void**)&p_f, g_f);
    cudaGetSymbolAddress((void**)&p_fn, g_fn);
    cudaGetSymbolAddress((void**)&p_wn, g_wn);
    cudaGetSymbolAddress((void**)&p_s1, g_s1);   cudaGetSymbolAddress((void**)&p_q1, g_q1);
    cudaGetSymbolAddress((void**)&p_sc1, g_sc1); cudaGetSymbolAddress((void**)&p_sh1, g_sh1);
    cudaGetSymbolAddress((void**)&p_s2, g_s2);   cudaGetSymbolAddress((void**)&p_q2, g_q2);
    cudaGetSymbolAddress((void**)&p_sc2, g_sc2); cudaGetSymbolAddress((void**)&p_sh2, g_sh2);
    cudaGetSymbolAddress((void**)&p_s3, g_s3);   cudaGetSymbolAddress((void**)&p_q3, g_q3);
    cudaGetSymbolAddress((void**)&p_sc3, g_sc3); cudaGetSymbolAddress((void**)&p_sh3, g_sh3);
    cudaGetSymbolAddress((void**)&p_s4, g_s4);   cudaGetSymbolAddress((void**)&p_q4, g_q4);
    cudaGetSymbolAddress((void**)&p_sc4, g_sc4); cudaGetSymbolAddress((void**)&p_sh4, g_sh4);

    zero_stats_k<<<1, 128>>>();

    // layer 1: conv (+stats) -> scale
    conv1_k<<<dim3(512, 13), 256>>>(x, w1);
    scale_k<<<1, 16>>>(p_s1, p_q1, g1, be1, p_sc1, p_sh1, 16, 1.f / (512.f * 3136.f));

    // layer 2: conv (bn1 fused in, +stats) -> scale; 16 OCs per block
    conv2_k<<<dim3(512, 2), 416>>>(w2);
    scale_k<<<1, 32>>>(p_s2, p_q2, g2, be2, p_sc2, p_sh2, 32, 1.f / (512.f * 784.f));

    // layer 3: 32->64, 28->26; 16 OCs per block
    conv3x3_k<32, 64, 28, 26, 352><<<dim3(512, 4), 352>>>(p_y2, w3, p_y3, p_sc2, p_sh2, p_s3, p_q3);
    scale_k<<<1, 64>>>(p_s3, p_q3, g3, be3, p_sc3, p_sh3, 64, 1.f / (512.f * 676.f));

    // layer 4: 64->128, 26->24; 16 OCs per block
    conv3x3_k<64, 128, 26, 24, 288><<<dim3(512, 8), 288>>>(p_y3, w4, p_y4, p_sc3, p_sh3, p_s4, p_q4);
    scale_k<<<1, 128>>>(p_s4, p_q4, g4, be4, p_sc4, p_sh4, 128, 1.f / (512.f * 576.f));

    // pool (bn4 fused) + normalize
    gap_k<<<512 * 128 / 8, 256>>>();
    l2norm_body_k<<<64, 256>>>(p_f, p_fn, 512);
    l2norm_body_k<<<(NCLS + 7) / 8, 256>>>(aw, p_wn, NCLS);

    // cosine logits (x64) + margin
    sgemm_k<<<dim3((NCLS + 127) / 128, 4), 256>>>(p_fn, p_wn, out);
    margin_k<<<2, 256>>>(gt, out);
}

// round 11
// speedup vs baseline: 1.6902x; 1.6902x over previous
#include <cuda_runtime.h>
#include <cuda_bf16.h>
#include <math.h>
#include <stdint.h>

#define NIMG 512
#define NCLS 100000

// ---------------- scratch (device globals; no allocation) ----------------
__device__ float g_y1[512 * 16 * 56 * 56];   // conv1 raw out
__device__ float g_y2[512 * 32 * 28 * 28];   // conv2 raw out
__device__ float g_y3[512 * 64 * 26 * 26];   // conv3 raw out
__device__ float g_y4[512 * 128 * 24 * 24];  // conv4 raw out
__device__ float g_f[512 * 128];
__device__ __nv_bfloat16 g_fh[512 * 128];    // normalized features hi
__device__ __nv_bfloat16 g_fl[512 * 128];    // normalized features lo
__device__ __nv_bfloat16 g_wh[NCLS * 128];   // normalized arc weights hi
__device__ __nv_bfloat16 g_wl[NCLS * 128];   // normalized arc weights lo
__device__ float g_s1[16], g_q1[16], g_sc1[16], g_sh1[16];
__device__ float g_s2[32], g_q2[32], g_sc2[32], g_sh2[32];
__device__ float g_s3[64], g_q3[64], g_sc3[64], g_sh3[64];
__device__ float g_s4[128], g_q4[128], g_sc4[128], g_sh4[128];

__global__ void zero_stats_k() {
    int t = threadIdx.x;
    if (t < 16)  { g_s1[t] = 0.f; g_q1[t] = 0.f; }
    if (t < 32)  { g_s2[t] = 0.f; g_q2[t] = 0.f; }
    if (t < 64)  { g_s3[t] = 0.f; g_q3[t] = 0.f; }
    if (t < 128) { g_s4[t] = 0.f; g_q4[t] = 0.f; }
}

// stats -> (scale, shift)
__global__ void scale_k(const float* __restrict__ s, const float* __restrict__ q,
                        const float* __restrict__ g, const float* __restrict__ be,
                        float* __restrict__ sc, float* __restrict__ sh, int C, float invCnt) {
    int c = threadIdx.x;
    if (c >= C) return;
    float mu = s[c] * invCnt;
    float var = fmaxf(q[c] * invCnt - mu * mu, 0.f);
    float a = g[c] * rsqrtf(var + 1e-5f);
    sc[c] = a;
    sh[c] = be[c] - mu * a;
}

// ---------------- conv1: 1->16, 4x4, s2, p1, 112 -> 56 (+fused stats) ----------------
__global__ __launch_bounds__(256) void conv1_k(const float* __restrict__ x,
                                               const float* __restrict__ w) {
    __shared__ float ws[256];  // [tap][oc]
    __shared__ float bs[16], bq[16];
    int tid = threadIdx.x;
    ws[(tid & 15) * 16 + (tid >> 4)] = w[tid];
    if (tid < 16) { bs[tid] = 0.f; bq[tid] = 0.f; }
    __syncthreads();
    int n = blockIdx.x;
    int p = blockIdx.y * 256 + tid;
    bool valid = (p < 3136);
    int pc = valid ? p : 3135;
    int oh = pc / 56, ow = pc % 56;
    const float* xin = x + (size_t)n * 112 * 112;
    float acc[16];
#pragma unroll
    for (int i = 0; i < 16; i++) acc[i] = 0.f;
#pragma unroll
    for (int kh = 0; kh < 4; kh++) {
        int ih = oh * 2 - 1 + kh;
        bool vh = ((unsigned)ih < 112u);
#pragma unroll
        for (int kw = 0; kw < 4; kw++) {
            int iw = ow * 2 - 1 + kw;
            float v = (vh && ((unsigned)iw < 112u)) ? xin[ih * 112 + iw] : 0.f;
            const float4* wp = (const float4*)(ws + (kh * 4 + kw) * 16);
#pragma unroll
            for (int q = 0; q < 4; q++) {
                float4 wv = wp[q];
                acc[4 * q + 0] += v * wv.x;
                acc[4 * q + 1] += v * wv.y;
                acc[4 * q + 2] += v * wv.z;
                acc[4 * q + 3] += v * wv.w;
            }
        }
    }
    float* out = g_y1 + (size_t)n * 16 * 3136;
    if (valid) {
#pragma unroll
        for (int oc = 0; oc < 16; oc++) out[oc * 3136 + p] = acc[oc];
    }
    int lane = tid & 31;
#pragma unroll
    for (int oc = 0; oc < 16; oc++) {
        float v = valid ? acc[oc] : 0.f;
        float q = v * v;
#pragma unroll
        for (int o = 16; o > 0; o >>= 1) {
            v += __shfl_xor_sync(0xffffffffu, v, o);
            q += __shfl_xor_sync(0xffffffffu, q, o);
        }
        if (lane == 0) { atomicAdd(&bs[oc], v); atomicAdd(&bq[oc], q); }
    }
    __syncthreads();
    if (tid < 16) { atomicAdd(&g_s1[tid], bs[tid]); atomicAdd(&g_q1[tid], bq[tid]); }
}

// ---------------- conv2: 16->32, 4x4, s2, p1, 56 -> 28 (bn1+relu fused in, stats out) --------
__global__ __launch_bounds__(416) void conv2_k(const float* __restrict__ w) {
    __shared__ float smi[2 * 58 * 58];
    __shared__ float smw[2 * 16 * 32];
    __shared__ float bs[32], bq[32];
    const int tid = threadIdx.x;
    const int n = blockIdx.x;

    for (int i = tid; i < 2 * 58 * 58; i += 416) smi[i] = 0.f;
    if (tid < 32) { bs[tid] = 0.f; bq[tid] = 0.f; }

    const int p0 = tid;
    const int p1 = tid + 416;
    const bool v1 = (p1 < 784);
    const int p1c = v1 ? p1 : 783;
    const int oh0 = p0 / 28, ow0 = p0 % 28;
    const int oh1 = p1c / 28, ow1 = p1c % 28;

    float acc0[32], acc1[32];
#pragma unroll
    for (int i = 0; i < 32; i++) { acc0[i] = 0.f; acc1[i] = 0.f; }

    const float* ain = g_y1 + (size_t)n * 16 * 3136;
    __syncthreads();

#pragma unroll 1
    for (int ic0 = 0; ic0 < 16; ic0 += 2) {
        float scA = g_sc1[ic0], shA = g_sh1[ic0];
        float scB = g_sc1[ic0 + 1], shB = g_sh1[ic0 + 1];
        for (int i = tid; i < 2 * 3136; i += 416) {
            int icl = i / 3136, r = i % 3136;
            int ih = r / 56, iw = r % 56;
            float raw = ain[(ic0 + icl) * 3136 + r];
            float sc = icl ? scB : scA, sh = icl ? shB : shA;
            smi[icl * 3364 + (ih + 1) * 58 + (iw + 1)] = fmaxf(fmaf(raw, sc, sh), 0.f);
        }
        for (int i = tid; i < 1024; i += 416) {
            int oc = i & 31, t = (i >> 5) & 15, icl = i >> 9;
            smw[i] = w[((oc * 16) + (ic0 + icl)) * 16 + t];
        }
        __syncthreads();
#pragma unroll 1
        for (int icl = 0; icl < 2; icl++) {
            const float* sip = smi + icl * 3364;
#pragma unroll
            for (int t = 0; t < 16; t++) {
                int kh = t >> 2, kw = t & 3;
                float in0 = sip[(oh0 * 2 + kh) * 58 + ow0 * 2 + kw];
                float in1 = sip[(oh1 * 2 + kh) * 58 + ow1 * 2 + kw];
                const float4* wp = (const float4*)(smw + ((icl * 16) + t) * 32);
#pragma unroll
                for (int q = 0; q < 8; q++) {
                    float4 wv = wp[q];
                    acc0[4 * q + 0] += in0 * wv.x; acc1[4 * q + 0] += in1 * wv.x;
                    acc0[4 * q + 1] += in0 * wv.y; acc1[4 * q + 1] += in1 * wv.y;
                    acc0[4 * q + 2] += in0 * wv.z; acc1[4 * q + 2] += in1 * wv.z;
                    acc0[4 * q + 3] += in0 * wv.w; acc1[4 * q + 3] += in1 * wv.w;
                }
            }
        }
        __syncthreads();
    }
    float* out = g_y2 + (size_t)n * 32 * 784;
#pragma unroll
    for (int oc = 0; oc < 32; oc++) {
        out[oc * 784 + p0] = acc0[oc];
        if (v1) out[oc * 784 + p1] = acc1[oc];
    }
    int lane = tid & 31;
#pragma unroll
    for (int oc = 0; oc < 32; oc++) {
        float v = acc0[oc] + (v1 ? acc1[oc] : 0.f);
        float q = acc0[oc] * acc0[oc] + (v1 ? acc1[oc] * acc1[oc] : 0.f);
#pragma unroll
        for (int o = 16; o > 0; o >>= 1) {
            v += __shfl_xor_sync(0xffffffffu, v, o);
            q += __shfl_xor_sync(0xffffffffu, q, o);
        }
        if (lane == 0) { atomicAdd(&bs[oc], v); atomicAdd(&bq[oc], q); }
    }
    __syncthreads();
    if (tid < 32) { atomicAdd(&g_s2[tid], bs[tid]); atomicAdd(&g_q2[tid], bq[tid]); }
}

// ---------------- generic 3x3 s1 p0 conv, 32 OCs/block, bn+relu fused in, stats out ---------
template <int IC, int OC, int IH, int OW, int THREADS>
__global__ __launch_bounds__(THREADS) void conv3x3_k(
    const float* __restrict__ act, const float* __restrict__ w, float* __restrict__ out,
    const float* __restrict__ isc, const float* __restrict__ ish,
    float* __restrict__ gs, float* __restrict__ gq) {
    constexpr int IHW = IH * IH;
    constexpr int PIX = OW * OW;
    __shared__ float smi[8 * IHW];
    __shared__ float smw[8 * 9 * 32];
    __shared__ float bs[32], bq[32];
    const int tid = threadIdx.x;
    const int n = blockIdx.x;
    const int ocb = blockIdx.y;

    if (tid < 32) { bs[tid] = 0.f; bq[tid] = 0.f; }

    const int p0 = tid;
    const int p1 = tid + THREADS;
    const bool v0 = (p0 < PIX);
    const bool v1 = (p1 < PIX);
    const int p0c = v0 ? p0 : (PIX - 1);
    const int p1c = v1 ? p1 : (PIX - 1);
    const int oh0 = p0c / OW, ow0 = p0c % OW;
    const int oh1 = p1c / OW, ow1 = p1c % OW;

    float acc0[32], acc1[32];
#pragma unroll
    for (int i = 0; i < 32; i++) { acc0[i] = 0.f; acc1[i] = 0.f; }

    const float* ain = act + (size_t)n * IC * IHW;

#pragma unroll 1
    for (int ic0 = 0; ic0 < IC; ic0 += 8) {
        for (int i = tid; i < 8 * IHW; i += THREADS) {
            int c = ic0 + i / IHW;
            smi[i] = fmaxf(fmaf(ain[ic0 * IHW + i], __ldg(&isc[c]), __ldg(&ish[c])), 0.f);
        }
        for (int i = tid; i < 2304; i += THREADS) {
            int oc = i & 31;
            int t = (i >> 5) % 9;
            int icl = i / 288;
            smw[i] = w[(((ocb * 32 + oc) * IC) + ic0 + icl) * 9 + t];
        }
        __syncthreads();
#pragma unroll 1
        for (int icl = 0; icl < 8; icl++) {
            const float* sip = smi + icl * IHW;
#pragma unroll
            for (int t = 0; t < 9; t++) {
                int kh = t / 3, kw = t % 3;
                float in0 = sip[(oh0 + kh) * IH + ow0 + kw];
                float in1 = sip[(oh1 + kh) * IH + ow1 + kw];
                const float4* wp = (const float4*)(smw + (icl * 9 + t) * 32);
#pragma unroll
                for (int q = 0; q < 8; q++) {
                    float4 wv = wp[q];
                    acc0[4 * q + 0] += in0 * wv.x; acc1[4 * q + 0] += in1 * wv.x;
                    acc0[4 * q + 1] += in0 * wv.y; acc1[4 * q + 1] += in1 * wv.y;
                    acc0[4 * q + 2] += in0 * wv.z; acc1[4 * q + 2] += in1 * wv.z;
                    acc0[4 * q + 3] += in0 * wv.w; acc1[4 * q + 3] += in1 * wv.w;
                }
            }
        }
        __syncthreads();
    }

    float* op = out + ((size_t)n * OC + ocb * 32) * PIX;
#pragma unroll
    for (int oc = 0; oc < 32; oc++) {
        if (v0) op[oc * PIX + p0] = acc0[oc];
        if (v1) op[oc * PIX + p1] = acc1[oc];
    }
    int lane = tid & 31;
#pragma unroll
    for (int oc = 0; oc < 32; oc++) {
        float a0 = v0 ? acc0[oc] : 0.f;
        float a1 = v1 ? acc1[oc] : 0.f;
        float v = a0 + a1;
        float q = a0 * a0 + a1 * a1;
#pragma unroll
        for (int o = 16; o > 0; o >>= 1) {
            v += __shfl_xor_sync(0xffffffffu, v, o);
            q += __shfl_xor_sync(0xffffffffu, q, o);
        }
        if (lane == 0) { atomicAdd(&bs[oc], v); atomicAdd(&bq[oc], q); }
    }
    __syncthreads();
    if (tid < 32) {
        atomicAdd(&gs[ocb * 32 + tid], bs[tid]);
        atomicAdd(&gq[ocb * 32 + tid], bq[tid]);
    }
}

// ---------------- GAP with bn4+relu fused: (512,128,24,24) -> (512,128) ----------------
__global__ void gap_k() {
    int pair = blockIdx.x * 8 + (threadIdx.x >> 5);
    int c = pair & 127;
    int lane = threadIdx.x & 31;
    float sc = g_sc4[c], sh = g_sh4[c];
    const float* p = g_y4 + (size_t)pair * 576;
    float s = 0.f;
    for (int i = lane; i < 576; i += 32) s += fmaxf(fmaf(p[i], sc, sh), 0.f);
#pragma unroll
    for (int o = 16; o > 0; o >>= 1) s += __shfl_xor_sync(0xffffffffu, s, o);
    if (lane == 0) g_f[pair] = s * (1.f / 576.f);
}

// ---------------- row-wise L2 normalize + split into bf16 hi/lo (K = 128) ----------------
__global__ void l2norm_split_k(const float* __restrict__ in,
                               __nv_bfloat16* __restrict__ oh,
                               __nv_bfloat16* __restrict__ ol, int rows) {
    int r = blockIdx.x * 8 + (threadIdx.x >> 5);
    if (r >= rows) return;
    int lane = threadIdx.x & 31;
    const float* p = in + (size_t)r * 128;
    float v0 = p[lane], v1 = p[lane + 32], v2 = p[lane + 64], v3 = p[lane + 96];
    float sq = v0 * v0 + v1 * v1 + v2 * v2 + v3 * v3;
#pragma unroll
    for (int o = 16; o > 0; o >>= 1) sq += __shfl_xor_sync(0xffffffffu, sq, o);
    float inv = 1.f / fmaxf(sqrtf(sq), 1e-12f);
    float v[4] = {v0 * inv, v1 * inv, v2 * inv, v3 * inv};
#pragma unroll
    for (int j = 0; j < 4; j++) {
        __nv_bfloat16 h = __float2bfloat16(v[j]);
        __nv_bfloat16 l = __float2bfloat16(v[j] - __bfloat162float(h));
        oh[(size_t)r * 128 + lane + 32 * j] = h;
        ol[(size_t)r * 128 + lane + 32 * j] = l;
    }
}

// ---------------- tensor-core bf16x3 GEMM: C = 64 * A(512x128) B(100000x128)^T ------------
__device__ __forceinline__ void ldsm4(uint32_t* r, uint32_t addr) {
    asm volatile("ldmatrix.sync.aligned.m8n8.x4.shared.b16 {%0,%1,%2,%3}, [%4];"
                 : "=r"(r[0]), "=r"(r[1]), "=r"(r[2]), "=r"(r[3]) : "r"(addr));
}
__device__ __forceinline__ void mma_bf16(float* c, const uint32_t* a, const uint32_t* b) {
    asm volatile(
        "mma.sync.aligned.m16n8k16.row.col.f32.bf16.bf16.f32 "
        "{%0,%1,%2,%3}, {%4,%5,%6,%7}, {%8,%9}, {%0,%1,%2,%3};"
        : "+f"(c[0]), "+f"(c[1]), "+f"(c[2]), "+f"(c[3])
        : "r"(a[0]), "r"(a[1]), "r"(a[2]), "r"(a[3]), "r"(b[0]), "r"(b[1]));
}

__global__ __launch_bounds__(256) void sgemm_tc_k(
    const __nv_bfloat16* __restrict__ Ah, const __nv_bfloat16* __restrict__ Al,
    const __nv_bfloat16* __restrict__ Bh, const __nv_bfloat16* __restrict__ Bl,
    float* __restrict__ C) {
    extern __shared__ __nv_bfloat16 sm[];
    __nv_bfloat16* As_h = sm;             // [128][128]
    __nv_bfloat16* As_l = sm + 16384;
    __nv_bfloat16* Bs_h = sm + 32768;
    __nv_bfloat16* Bs_l = sm + 49152;
    const int tid = threadIdx.x;
    const int bm = blockIdx.y * 128;
    const int bn = blockIdx.x * 128;
    const int r = tid >> 1, half = tid & 1;

    // ---- stage whole K=128 panels (XOR-swizzled 16B chunks: c' = c ^ (row%8)) ----
    {
        const uint4* sa_h = (const uint4*)(Ah + (size_t)(bm + r) * 128);
        const uint4* sa_l = (const uint4*)(Al + (size_t)(bm + r) * 128);
        uint4* da_h = (uint4*)As_h;
        uint4* da_l = (uint4*)As_l;
#pragma unroll
        for (int i = 0; i < 8; i++) {
            int c = half * 8 + i, cs = c ^ (r & 7);
            da_h[r * 16 + cs] = sa_h[c];
            da_l[r * 16 + cs] = sa_l[c];
        }
        int n = bn + r;
        bool v = (n < NCLS);
        const uint4* sb_h = (const uint4*)(Bh + (size_t)n * 128);
        const uint4* sb_l = (const uint4*)(Bl + (size_t)n * 128);
        uint4* db_h = (uint4*)Bs_h;
        uint4* db_l = (uint4*)Bs_l;
        uint4 z = make_uint4(0u, 0u, 0u, 0u);
#pragma unroll
        for (int i = 0; i < 8; i++) {
            int c = half * 8 + i, cs = c ^ (r & 7);
            db_h[r * 16 + cs] = v ? sb_h[c] : z;
            db_l[r * 16 + cs] = v ? sb_l[c] : z;
        }
    }
    __syncthreads();

    const int w = tid >> 5, lane = tid & 31;
    const int wm = w & 3, wn = w >> 2;  // 4 m-warps x 2 n-warps; warp tile 32m x 64n

    float acc[2][8][4];
#pragma unroll
    for (int a = 0; a < 2; a++)
#pragma unroll
        for (int b = 0; b < 8; b++)
#pragma unroll
            for (int d = 0; d < 4; d++) acc[a][b][d] = 0.f;

    uint32_t ash = (uint32_t)__cvta_generic_to_shared(As_h);
    uint32_t asl = (uint32_t)__cvta_generic_to_shared(As_l);
    uint32_t bsh = (uint32_t)__cvta_generic_to_shared(Bs_h);
    uint32_t bsl = (uint32_t)__cvta_generic_to_shared(Bs_l);

#pragma unroll
    for (int kb = 0; kb < 8; kb++) {
        uint32_t ah[2][4], al[2][4];
#pragma unroll
        for (int mt = 0; mt < 2; mt++) {
            int ml = wm * 32 + mt * 16 + (lane & 15);
            int cs = (2 * kb + (lane >> 4)) ^ (ml & 7);
            uint32_t off = (uint32_t)(ml * 256 + cs * 16);
            ldsm4(ah[mt], ash + off);
            ldsm4(al[mt], asl + off);
        }
        uint32_t bh[8][2], bl[8][2];
#pragma unroll
        for (int np = 0; np < 4; np++) {
            int nl = wn * 64 + np * 16 + (lane & 7) + ((lane >> 4) << 3);
            int cs = (2 * kb + ((lane >> 3) & 1)) ^ (nl & 7);
            uint32_t off = (uint32_t)(nl * 256 + cs * 16);
            uint32_t t[4];
            ldsm4(t, bsh + off);
            bh[2 * np][0] = t[0]; bh[2 * np][1] = t[1];
            bh[2 * np + 1][0] = t[2]; bh[2 * np + 1][1] = t[3];
            ldsm4(t, bsl + off);
            bl[2 * np][0] = t[0]; bl[2 * np][1] = t[1];
            bl[2 * np + 1][0] = t[2]; bl[2 * np + 1][1] = t[3];
        }
#pragma unroll
        for (int mt = 0; mt < 2; mt++)
#pragma unroll
            for (int nt = 0; nt < 8; nt++) {
                mma_bf16(acc[mt][nt], ah[mt], bh[nt]);  // hi*hi
                mma_bf16(acc[mt][nt], ah[mt], bl[nt]);  // hi*lo
                mma_bf16(acc[mt][nt], al[mt], bh[nt]);  // lo*hi
            }
    }

    // ---- epilogue: x64, float2 stores ----
#pragma unroll
    for (int mt = 0; mt < 2; mt++) {
#pragma unroll
        for (int nt = 0; nt < 8; nt++) {
            int m = bm + wm * 32 + mt * 16 + (lane >> 2);
            int n = bn + wn * 64 + nt * 8 + ((lane & 3) << 1);
            if (n < NCLS) {
                float* cp0 = C + (size_t)m * NCLS + n;
                *(float2*)cp0 = make_float2(64.f * acc[mt][nt][0], 64.f * acc[mt][nt][1]);
                float* cp1 = C + (size_t)(m + 8) * NCLS + n;
                *(float2*)cp1 = make_float2(64.f * acc[mt][nt][2], 64.f * acc[mt][nt][3]);
            }
        }
    }
}

// ---------------- ArcFace margin fix-up ----------------
__global__ void margin_k(const int* __restrict__ gt, float* __restrict__ out) {
    int n = blockIdx.x * 256 + threadIdx.x;
    if (n >= NIMG) return;
    int c = gt[n];
    size_t idx = (size_t)n * NCLS + c;
    float v = out[idx] * (1.f / 64.f);
    float s = sqrtf(fmaxf(1.f - v * v, 0.f));
    const float cm = 0.87758256189037271612f;  // cos(0.5)
    const float sm = 0.47942553860420300027f;  // sin(0.5)
    out[idx] = 64.f * (v * cm - s * sm);
}

// ---------------- launch ----------------
extern "C" void kernel_launch(void* const* d_in, const int* in_sizes, int n_in,
                              void* d_out, int out_size) {
    const float* x  = (const float*)d_in[0];
    const int*   gt = (const int*)d_in[1];
    const float* w1 = (const float*)d_in[2];
    const float* g1 = (const float*)d_in[4];
    const float* be1 = (const float*)d_in[5];
    const float* w2 = (const float*)d_in[6];
    const float* g2 = (const float*)d_in[8];
    const float* be2 = (const float*)d_in[9];
    const float* w3 = (const float*)d_in[10];
    const float* g3 = (const float*)d_in[12];
    const float* be3 = (const float*)d_in[13];
    const float* w4 = (const float*)d_in[14];
    const float* g4 = (const float*)d_in[16];
    const float* be4 = (const float*)d_in[17];
    const float* aw = (const float*)d_in[18];
    float* out = (float*)d_out;

    // Resolve REAL device addresses of __device__ globals.
    float *p_y2, *p_y3, *p_y4, *p_f;
    __nv_bfloat16 *p_fh, *p_fl, *p_wh, *p_wl;
    float *p_s1, *p_q1, *p_sc1, *p_sh1;
    float *p_s2, *p_q2, *p_sc2, *p_sh2;
    float *p_s3, *p_q3, *p_sc3, *p_sh3;
    float *p_s4, *p_q4, *p_sc4, *p_sh4;
    cudaGetSymbolAddress((void**)&p_y2, g_y2);
    cudaGetSymbolAddress((void**)&p_y3, g_y3);
    cudaGetSymbolAddress((void**)&p_y4, g_y4);
    cudaGetSymbolAddress((void**)&p_f, g_f);
    cudaGetSymbolAddress((void**)&p_fh, g_fh);
    cudaGetSymbolAddress((void**)&p_fl, g_fl);
    cudaGetSymbolAddress((void**)&p_wh, g_wh);
    cudaGetSymbolAddress((void**)&p_wl, g_wl);
    cudaGetSymbolAddress((void**)&p_s1, g_s1);   cudaGetSymbolAddress((void**)&p_q1, g_q1);
    cudaGetSymbolAddress((void**)&p_sc1, g_sc1); cudaGetSymbolAddress((void**)&p_sh1, g_sh1);
    cudaGetSymbolAddress((void**)&p_s2, g_s2);   cudaGetSymbolAddress((void**)&p_q2, g_q2);
    cudaGetSymbolAddress((void**)&p_sc2, g_sc2); cudaGetSymbolAddress((void**)&p_sh2, g_sh2);
    cudaGetSymbolAddress((void**)&p_s3, g_s3);   cudaGetSymbolAddress((void**)&p_q3, g_q3);
    cudaGetSymbolAddress((void**)&p_sc3, g_sc3); cudaGetSymbolAddress((void**)&p_sh3, g_sh3);
    cudaGetSymbolAddress((void**)&p_s4, g_s4);   cudaGetSymbolAddress((void**)&p_q4, g_q4);
    cudaGetSymbolAddress((void**)&p_sc4, g_sc4); cudaGetSymbolAddress((void**)&p_sh4, g_sh4);

    // allow 128KB dynamic smem for the tensor-core GEMM (attribute set, not an allocation)
    cudaFuncSetAttribute(sgemm_tc_k, cudaFuncAttributeMaxDynamicSharedMemorySize, 131072);

    zero_stats_k<<<1, 128>>>();

    // layer 1: conv (+stats) -> scale
    conv1_k<<<dim3(512, 13), 256>>>(x, w1);
    scale_k<<<1, 16>>>(p_s1, p_q1, g1, be1, p_sc1, p_sh1, 16, 1.f / (512.f * 3136.f));

    // layer 2: conv (bn1 fused in, +stats) -> scale
    conv2_k<<<512, 416>>>(w2);
    scale_k<<<1, 32>>>(p_s2, p_q2, g2, be2, p_sc2, p_sh2, 32, 1.f / (512.f * 784.f));

    // layer 3: 32->64, 28->26
    conv3x3_k<32, 64, 28, 26, 352><<<dim3(512, 2), 352>>>(p_y2, w3, p_y3, p_sc2, p_sh2, p_s3, p_q3);
    scale_k<<<1, 64>>>(p_s3, p_q3, g3, be3, p_sc3, p_sh3, 64, 1.f / (512.f * 676.f));

    // layer 4: 64->128, 26->24
    conv3x3_k<64, 128, 26, 24, 288><<<dim3(512, 4), 288>>>(p_y3, w4, p_y4, p_sc3, p_sh3, p_s4, p_q4);
    scale_k<<<1, 128>>>(p_s4, p_q4, g4, be4, p_sc4, p_sh4, 128, 1.f / (512.f * 576.f));

    // pool (bn4 fused) + normalize + bf16 hi/lo split
    gap_k<<<512 * 128 / 8, 256>>>();
    l2norm_split_k<<<64, 256>>>(p_f, p_fh, p_fl, 512);
    l2norm_split_k<<<(NCLS + 7) / 8, 256>>>(aw, p_wh, p_wl, NCLS);

    // cosine logits (x64) via bf16x3 tensor cores + margin
    sgemm_tc_k<<<dim3((NCLS + 127) / 128, 4), 256, 131072>>>(p_fh, p_fl, p_wh, p_wl, out);
    margin_k<<<2, 256>>>(gt, out);
}

// round 13
// speedup vs baseline: 2.4706x; 1.4617x over previous
#include <cuda_runtime.h>
#include <cuda_bf16.h>
#include <math.h>
#include <stdint.h>

#define NIMG 512
#define NCLS 100000

// ---------------- scratch (device globals; no allocation) ----------------
__device__ float g_y1[512 * 16 * 56 * 56];   // conv1 raw out
__device__ float g_y2[512 * 32 * 28 * 28];   // conv2 raw out
__device__ float g_y3[512 * 64 * 26 * 26];   // conv3 raw out
__device__ float g_y4[512 * 576 * 128];      // conv4 raw out, layout [n][pix][oc]
__device__ float g_f[512 * 128];
__device__ __nv_bfloat16 g_fh[512 * 128];    // normalized features hi
__device__ __nv_bfloat16 g_fl[512 * 128];    // normalized features lo
__device__ __nv_bfloat16 g_wh[NCLS * 128];   // normalized arc weights hi
__device__ __nv_bfloat16 g_wl[NCLS * 128];   // normalized arc weights lo
__device__ __nv_bfloat16 g_w4h[4 * 9 * 128 * 16];  // conv4 weights bf16 hi [chunk][tap][oc][icl]
__device__ __nv_bfloat16 g_w4l[4 * 9 * 128 * 16];  // conv4 weights bf16 lo
__device__ float g_s1[16], g_q1[16], g_sc1[16], g_sh1[16];
__device__ float g_s2[32], g_q2[32], g_sc2[32], g_sh2[32];
__device__ float g_s3[64], g_q3[64], g_sc3[64], g_sh3[64];
__device__ float g_s4[128], g_q4[128], g_sc4[128], g_sh4[128];

__global__ void zero_stats_k() {
    int t = threadIdx.x;
    if (t < 16)  { g_s1[t] = 0.f; g_q1[t] = 0.f; }
    if (t < 32)  { g_s2[t] = 0.f; g_q2[t] = 0.f; }
    if (t < 64)  { g_s3[t] = 0.f; g_q3[t] = 0.f; }
    if (t < 128) { g_s4[t] = 0.f; g_q4[t] = 0.f; }
}

// stats -> (scale, shift)
__global__ void scale_k(const float* __restrict__ s, const float* __restrict__ q,
                        const float* __restrict__ g, const float* __restrict__ be,
                        float* __restrict__ sc, float* __restrict__ sh, int C, float invCnt) {
    int c = threadIdx.x;
    if (c >= C) return;
    float mu = s[c] * invCnt;
    float var = fmaxf(q[c] * invCnt - mu * mu, 0.f);
    float a = g[c] * rsqrtf(var + 1e-5f);
    sc[c] = a;
    sh[c] = be[c] - mu * a;
}

// ---------------- conv1: 1->16, 4x4, s2, p1, 112 -> 56 (+fused stats) ----------------
__global__ __launch_bounds__(256) void conv1_k(const float* __restrict__ x,
                                               const float* __restrict__ w) {
    __shared__ float ws[256];  // [tap][oc]
    __shared__ float bs[16], bq[16];
    int tid = threadIdx.x;
    ws[(tid & 15) * 16 + (tid >> 4)] = w[tid];
    if (tid < 16) { bs[tid] = 0.f; bq[tid] = 0.f; }
    __syncthreads();
    int n = blockIdx.x;
    int p = blockIdx.y * 256 + tid;
    bool valid = (p < 3136);
    int pc = valid ? p : 3135;
    int oh = pc / 56, ow = pc % 56;
    const float* xin = x + (size_t)n * 112 * 112;
    float acc[16];
#pragma unroll
    for (int i = 0; i < 16; i++) acc[i] = 0.f;
#pragma unroll
    for (int kh = 0; kh < 4; kh++) {
        int ih = oh * 2 - 1 + kh;
        bool vh = ((unsigned)ih < 112u);
#pragma unroll
        for (int kw = 0; kw < 4; kw++) {
            int iw = ow * 2 - 1 + kw;
            float v = (vh && ((unsigned)iw < 112u)) ? xin[ih * 112 + iw] : 0.f;
            const float4* wp = (const float4*)(ws + (kh * 4 + kw) * 16);
#pragma unroll
            for (int q = 0; q < 4; q++) {
                float4 wv = wp[q];
                acc[4 * q + 0] += v * wv.x;
                acc[4 * q + 1] += v * wv.y;
                acc[4 * q + 2] += v * wv.z;
                acc[4 * q + 3] += v * wv.w;
            }
        }
    }
    float* out = g_y1 + (size_t)n * 16 * 3136;
    if (valid) {
#pragma unroll
        for (int oc = 0; oc < 16; oc++) out[oc * 3136 + p] = acc[oc];
    }
    int lane = tid & 31;
#pragma unroll
    for (int oc = 0; oc < 16; oc++) {
        float v = valid ? acc[oc] : 0.f;
        float q = v * v;
#pragma unroll
        for (int o = 16; o > 0; o >>= 1) {
            v += __shfl_xor_sync(0xffffffffu, v, o);
            q += __shfl_xor_sync(0xffffffffu, q, o);
        }
        if (lane == 0) { atomicAdd(&bs[oc], v); atomicAdd(&bq[oc], q); }
    }
    __syncthreads();
    if (tid < 16) { atomicAdd(&g_s1[tid], bs[tid]); atomicAdd(&g_q1[tid], bq[tid]); }
}

// ---------------- conv2: 16->32, 4x4, s2, p1, 56 -> 28 (bn1+relu fused in, stats out) --------
__global__ __launch_bounds__(416) void conv2_k(const float* __restrict__ w) {
    __shared__ float smi[2 * 58 * 58];
    __shared__ float smw[2 * 16 * 32];
    __shared__ float bs[32], bq[32];
    const int tid = threadIdx.x;
    const int n = blockIdx.x;

    for (int i = tid; i < 2 * 58 * 58; i += 416) smi[i] = 0.f;
    if (tid < 32) { bs[tid] = 0.f; bq[tid] = 0.f; }

    const int p0 = tid;
    const int p1 = tid + 416;
    const bool v1 = (p1 < 784);
    const int p1c = v1 ? p1 : 783;
    const int oh0 = p0 / 28, ow0 = p0 % 28;
    const int oh1 = p1c / 28, ow1 = p1c % 28;

    float acc0[32], acc1[32];
#pragma unroll
    for (int i = 0; i < 32; i++) { acc0[i] = 0.f; acc1[i] = 0.f; }

    const float* ain = g_y1 + (size_t)n * 16 * 3136;
    __syncthreads();

#pragma unroll 1
    for (int ic0 = 0; ic0 < 16; ic0 += 2) {
        float scA = g_sc1[ic0], shA = g_sh1[ic0];
        float scB = g_sc1[ic0 + 1], shB = g_sh1[ic0 + 1];
        for (int i = tid; i < 2 * 3136; i += 416) {
            int icl = i / 3136, r = i % 3136;
            int ih = r / 56, iw = r % 56;
            float raw = ain[(ic0 + icl) * 3136 + r];
            float sc = icl ? scB : scA, sh = icl ? shB : shA;
            smi[icl * 3364 + (ih + 1) * 58 + (iw + 1)] = fmaxf(fmaf(raw, sc, sh), 0.f);
        }
        for (int i = tid; i < 1024; i += 416) {
            int oc = i & 31, t = (i >> 5) & 15, icl = i >> 9;
            smw[i] = w[((oc * 16) + (ic0 + icl)) * 16 + t];
        }
        __syncthreads();
#pragma unroll 1
        for (int icl = 0; icl < 2; icl++) {
            const float* sip = smi + icl * 3364;
#pragma unroll
            for (int t = 0; t < 16; t++) {
                int kh = t >> 2, kw = t & 3;
                float in0 = sip[(oh0 * 2 + kh) * 58 + ow0 * 2 + kw];
                float in1 = sip[(oh1 * 2 + kh) * 58 + ow1 * 2 + kw];
                const float4* wp = (const float4*)(smw + ((icl * 16) + t) * 32);
#pragma unroll
                for (int q = 0; q < 8; q++) {
                    float4 wv = wp[q];
                    acc0[4 * q + 0] += in0 * wv.x; acc1[4 * q + 0] += in1 * wv.x;
                    acc0[4 * q + 1] += in0 * wv.y; acc1[4 * q + 1] += in1 * wv.y;
                    acc0[4 * q + 2] += in0 * wv.z; acc1[4 * q + 2] += in1 * wv.z;
                    acc0[4 * q + 3] += in0 * wv.w; acc1[4 * q + 3] += in1 * wv.w;
                }
            }
        }
        __syncthreads();
    }
    float* out = g_y2 + (size_t)n * 32 * 784;
#pragma unroll
    for (int oc = 0; oc < 32; oc++) {
        out[oc * 784 + p0] = acc0[oc];
        if (v1) out[oc * 784 + p1] = acc1[oc];
    }
    int lane = tid & 31;
#pragma unroll
    for (int oc = 0; oc < 32; oc++) {
        float v = acc0[oc] + (v1 ? acc1[oc] : 0.f);
        float q = acc0[oc] * acc0[oc] + (v1 ? acc1[oc] * acc1[oc] : 0.f);
#pragma unroll
        for (int o = 16; o > 0; o >>= 1) {
            v += __shfl_xor_sync(0xffffffffu, v, o);
            q += __shfl_xor_sync(0xffffffffu, q, o);
        }
        if (lane == 0) { atomicAdd(&bs[oc], v); atomicAdd(&bq[oc], q); }
    }
    __syncthreads();
    if (tid < 32) { atomicAdd(&g_s2[tid], bs[tid]); atomicAdd(&g_q2[tid], bq[tid]); }
}

// ---------------- conv3 (fp32): 3x3 s1 p0, 32 OCs/block, bn+relu fused in, stats out ---------
template <int IC, int OC, int IH, int OW, int THREADS>
__global__ __launch_bounds__(THREADS) void conv3x3_k(
    const float* __restrict__ act, const float* __restrict__ w, float* __restrict__ out,
    const float* __restrict__ isc, const float* __restrict__ ish,
    float* __restrict__ gs, float* __restrict__ gq) {
    constexpr int IHW = IH * IH;
    constexpr int PIX = OW * OW;
    __shared__ float smi[8 * IHW];
    __shared__ float smw[8 * 9 * 32];
    __shared__ float bs[32], bq[32];
    const int tid = threadIdx.x;
    const int n = blockIdx.x;
    const int ocb = blockIdx.y;

    if (tid < 32) { bs[tid] = 0.f; bq[tid] = 0.f; }

    const int p0 = tid;
    const int p1 = tid + THREADS;
    const bool v0 = (p0 < PIX);
    const bool v1 = (p1 < PIX);
    const int p0c = v0 ? p0 : (PIX - 1);
    const int p1c = v1 ? p1 : (PIX - 1);
    const int oh0 = p0c / OW, ow0 = p0c % OW;
    const int oh1 = p1c / OW, ow1 = p1c % OW;

    float acc0[32], acc1[32];
#pragma unroll
    for (int i = 0; i < 32; i++) { acc0[i] = 0.f; acc1[i] = 0.f; }

    const float* ain = act + (size_t)n * IC * IHW;

#pragma unroll 1
    for (int ic0 = 0; ic0 < IC; ic0 += 8) {
        for (int i = tid; i < 8 * IHW; i += THREADS) {
            int c = ic0 + i / IHW;
            smi[i] = fmaxf(fmaf(ain[ic0 * IHW + i], __ldg(&isc[c]), __ldg(&ish[c])), 0.f);
        }
        for (int i = tid; i < 2304; i += THREADS) {
            int oc = i & 31;
            int t = (i >> 5) % 9;
            int icl = i / 288;
            smw[i] = w[(((ocb * 32 + oc) * IC) + ic0 + icl) * 9 + t];
        }
        __syncthreads();
#pragma unroll 1
        for (int icl = 0; icl < 8; icl++) {
            const float* sip = smi + icl * IHW;
#pragma unroll
            for (int t = 0; t < 9; t++) {
                int kh = t / 3, kw = t % 3;
                float in0 = sip[(oh0 + kh) * IH + ow0 + kw];
                float in1 = sip[(oh1 + kh) * IH + ow1 + kw];
                const float4* wp = (const float4*)(smw + (icl * 9 + t) * 32);
#pragma unroll
                for (int q = 0; q < 8; q++) {
                    float4 wv = wp[q];
                    acc0[4 * q + 0] += in0 * wv.x; acc1[4 * q + 0] += in1 * wv.x;
                    acc0[4 * q + 1] += in0 * wv.y; acc1[4 * q + 1] += in1 * wv.y;
                    acc0[4 * q + 2] += in0 * wv.z; acc1[4 * q + 2] += in1 * wv.z;
                    acc0[4 * q + 3] += in0 * wv.w; acc1[4 * q + 3] += in1 * wv.w;
                }
            }
        }
        __syncthreads();
    }

    float* op = out + ((size_t)n * OC + ocb * 32) * PIX;
#pragma unroll
    for (int oc = 0; oc < 32; oc++) {
        if (v0) op[oc * PIX + p0] = acc0[oc];
        if (v1) op[oc * PIX + p1] = acc1[oc];
    }
    int lane = tid & 31;
#pragma unroll
    for (int oc = 0; oc < 32; oc++) {
        float a0 = v0 ? acc0[oc] : 0.f;
        float a1 = v1 ? acc1[oc] : 0.f;
        float v = a0 + a1;
        float q = a0 * a0 + a1 * a1;
#pragma unroll
        for (int o = 16; o > 0; o >>= 1) {
            v += __shfl_xor_sync(0xffffffffu, v, o);
            q += __shfl_xor_sync(0xffffffffu, q, o);
        }
        if (lane == 0) { atomicAdd(&bs[oc], v); atomicAdd(&bq[oc], q); }
    }
    __syncthreads();
    if (tid < 32) {
        atomicAdd(&gs[ocb * 32 + tid], bs[tid]);
        atomicAdd(&gq[ocb * 32 + tid], bq[tid]);
    }
}

// ---------------- conv4 weight prep: fp32 OIHW -> bf16 hi/lo [chunk][tap][oc][icl] ----------
__global__ void prep_w4_k(const float* __restrict__ w4,
                          __nv_bfloat16* __restrict__ Wh, __nv_bfloat16* __restrict__ Wl) {
    int i = blockIdx.x * 256 + threadIdx.x;
    if (i >= 4 * 9 * 128 * 16) return;
    int icl = i & 15;
    int oc = (i >> 4) & 127;
    int rest = i >> 11;       // chunk*9 + tap
    int t = rest % 9;
    int ch = rest / 9;
    float v = w4[((size_t)oc * 64 + ch * 16 + icl) * 9 + t];
    __nv_bfloat16 h = __float2bfloat16(v);
    Wh[i] = h;
    Wl[i] = __float2bfloat16(v - __bfloat162float(h));
}

// ---------------- mma helpers (proven in sgemm_tc_k) ----------------
__device__ __forceinline__ void ldsm4(uint32_t* r, uint32_t addr) {
    asm volatile("ldmatrix.sync.aligned.m8n8.x4.shared.b16 {%0,%1,%2,%3}, [%4];"
                 : "=r"(r[0]), "=r"(r[1]), "=r"(r[2]), "=r"(r[3]) : "r"(addr));
}
__device__ __forceinline__ void mma_bf16(float* c, const uint32_t* a, const uint32_t* b) {
    asm volatile(
        "mma.sync.aligned.m16n8k16.row.col.f32.bf16.bf16.f32 "
        "{%0,%1,%2,%3}, {%4,%5,%6,%7}, {%8,%9}, {%0,%1,%2,%3};"
        : "+f"(c[0]), "+f"(c[1]), "+f"(c[2]), "+f"(c[3])
        : "r"(a[0]), "r"(a[1]), "r"(a[2]), "r"(a[3]), "r"(b[0]), "r"(b[1]));
}

// ---------------- conv4 tensor-core shifted-GEMM (bf16x3) ----------------
// Per block: (image n, m-tile of 192 output pixels = 8 output rows).
// K loop: 4 IC-chunks of 16; inner: 9 taps, each one k16 MMA step.
// Input staged pixel-major S[260][16] bf16 hi/lo (bn3+relu fused); taps = row shifts.
// Output: g_y4 [n][576][128] fp32, written coalesced via smem transpose.
__global__ __launch_bounds__(256) void conv4_tc_k(
    const float* __restrict__ act,              // g_y3 [512][64][676] raw
    const __nv_bfloat16* __restrict__ Wh,
    const __nv_bfloat16* __restrict__ Wl,
    const float* __restrict__ isc, const float* __restrict__ ish,
    float* __restrict__ out) {
    extern __shared__ char smraw[];
    __nv_bfloat16* S_h = (__nv_bfloat16*)smraw;                  // 260*32B = 8320 -> pad 8448
    __nv_bfloat16* S_l = (__nv_bfloat16*)(smraw + 8448);
    __nv_bfloat16* W_hs = (__nv_bfloat16*)(smraw + 16896);       // 9*128*32B = 36864
    __nv_bfloat16* W_ls = (__nv_bfloat16*)(smraw + 16896 + 36864);
    float* Cs = (float*)smraw;                                   // epilogue reuse: 192*128*4 = 98304

    const int tid = threadIdx.x;
    const int n = blockIdx.x;
    const int mt3 = blockIdx.y;   // 0..2, 192 pixels each
    const int oh0 = mt3 * 8;      // first output row of tile
    const int w = tid >> 5, lane = tid & 31;
    const int wm = w & 3, wn = w >> 2;  // warp tile 48m x 64n

    // per-lane A row bases (local input pixel index for tap (0,0))
    int abase[3];
#pragma unroll
    for (int mt = 0; mt < 3; mt++) {
        int p = wm * 48 + mt * 16 + (lane & 15);  // local output pixel 0..191
        int oh = p / 24, ow = p % 24;
        abase[mt] = oh * 26 + ow;
    }

    float acc[3][8][4];
#pragma unroll
    for (int a = 0; a < 3; a++)
#pragma unroll
        for (int b = 0; b < 8; b++)
#pragma unroll
            for (int d = 0; d < 4; d++) acc[a][b][d] = 0.f;

    uint32_t sSh = (uint32_t)__cvta_generic_to_shared(S_h);
    uint32_t sSl = (uint32_t)__cvta_generic_to_shared(S_l);
    uint32_t sWh = (uint32_t)__cvta_generic_to_shared(W_hs);
    uint32_t sWl = (uint32_t)__cvta_generic_to_shared(W_ls);

#pragma unroll 1
    for (int ch = 0; ch < 4; ch++) {
        // ---- stage S: 16 ICs x 260 input pixels, bn+relu, hi/lo split ----
#pragma unroll 1
        for (int icl = 0; icl < 16; icl++) {
            int c = ch * 16 + icl;
            const float* pl = act + ((size_t)n * 64 + c) * 676 + oh0 * 26;
            float sc = __ldg(&isc[c]), sh = __ldg(&ish[c]);
            int cidx = icl >> 3, e = icl & 7;
            for (int j = tid; j < 260; j += 256) {
                float v = fmaxf(fmaf(pl[j], sc, sh), 0.f);
                __nv_bfloat16 h = __float2bfloat16(v);
                __nv_bfloat16 l = __float2bfloat16(v - __bfloat162float(h));
                int off = j * 16 + (cidx ^ (j & 1)) * 8 + e;  // bf16 units
                S_h[off] = h;
                S_l[off] = l;
            }
        }
        // ---- stage W chunk: 2304 uint4 (hi) + 2304 (lo), swizzled ----
        {
            const uint4* srch = (const uint4*)(Wh + (size_t)ch * 9 * 128 * 16);
            const uint4* srcl = (const uint4*)(Wl + (size_t)ch * 9 * 128 * 16);
            uint4* dsth = (uint4*)W_hs;
            uint4* dstl = (uint4*)W_ls;
            for (int i = tid; i < 2304; i += 256) {
                int row = i >> 1, c = i & 1;
                int d = row * 2 + (c ^ (row & 1));
                dsth[d] = srch[i];
                dstl[d] = srcl[i];
            }
        }
        __syncthreads();

        // ---- 9 taps, one k16 step each ----
#pragma unroll 3
        for (int t = 0; t < 9; t++) {
            const int toff = (t / 3) * 26 + (t % 3);
            uint32_t ah[3][4], al[3][4];
#pragma unroll
            for (int mt = 0; mt < 3; mt++) {
                int row = abase[mt] + toff;
                uint32_t off = (uint32_t)(row * 32 + (((lane >> 4) ^ (row & 1)) * 16));
                ldsm4(ah[mt], sSh + off);
                ldsm4(al[mt], sSl + off);
            }
#pragma unroll
            for (int np = 0; np < 4; np++) {
                int nl = wn * 64 + np * 16 + (lane & 7) + ((lane >> 4) << 3);
                int cs = ((lane >> 3) & 1) ^ (nl & 1);
                uint32_t off = (uint32_t)((t * 128 + nl) * 32 + cs * 16);
                uint32_t th[4], tl[4];
                ldsm4(th, sWh + off);
                ldsm4(tl, sWl + off);
#pragma unroll
                for (int mt = 0; mt < 3; mt++) {
                    mma_bf16(acc[mt][2 * np], ah[mt], th);       // hi*hi (b = th[0..1])
                    mma_bf16(acc[mt][2 * np], ah[mt], tl);       // hi*lo
                    mma_bf16(acc[mt][2 * np], al[mt], th);       // lo*hi
                    mma_bf16(acc[mt][2 * np + 1], ah[mt], th + 2);
                    mma_bf16(acc[mt][2 * np + 1], ah[mt], tl + 2);
                    mma_bf16(acc[mt][2 * np + 1], al[mt], th + 2);
                }
            }
        }
        __syncthreads();  // S/W reused next chunk (or Cs in epilogue)
    }

    // ---- epilogue: acc -> smem [192 p][128 oc] (chunk-XOR swizzle) -> coalesced GST ----
#pragma unroll
    for (int mt = 0; mt < 3; mt++) {
#pragma unroll
        for (int nt = 0; nt < 8; nt++) {
            int r0 = wm * 48 + mt * 16 + (lane >> 2);
            int c0 = wn * 64 + nt * 8 + ((lane & 3) << 1);
            int ph0 = ((c0 >> 2) ^ (r0 & 7));
            *(float2*)&Cs[r0 * 128 + ph0 * 4 + (c0 & 3)] = make_float2(acc[mt][nt][0], acc[mt][nt][1]);
            int r1 = r0 + 8;
            int ph1 = ((c0 >> 2) ^ (r1 & 7));
            *(float2*)&Cs[r1 * 128 + ph1 * 4 + (c0 & 3)] = make_float2(acc[mt][nt][2], acc[mt][nt][3]);
        }
    }
    __syncthreads();
    float* og = out + ((size_t)n * 576 + mt3 * 192) * 128;
    for (int i = tid; i < 6144; i += 256) {  // 192 rows * 32 uint4
        int p = i >> 5, cc = i & 31;
        ((uint4*)og)[i] = ((uint4*)Cs)[p * 32 + (cc ^ (p & 7))];
    }
}

// ---------------- stats for layer 4 (layout [n][pix][oc]) ----------------
__global__ void stats4n_k() {
    int n = blockIdx.x;
    int oc = threadIdx.x;
    const float* p = g_y4 + (size_t)n * 576 * 128 + oc;
    float s = 0.f, q = 0.f;
#pragma unroll 4
    for (int i = 0; i < 576; i++) {
        float v = p[i * 128];
        s += v;
        q += v * v;
    }
    atomicAdd(&g_s4[oc], s);
    atomicAdd(&g_q4[oc], q);
}

// ---------------- GAP with bn4+relu fused (layout [n][pix][oc]) ----------------
__global__ void gap_n_k() {
    int n = blockIdx.x;
    int oc = threadIdx.x;
    float sc = g_sc4[oc], sh = g_sh4[oc];
    const float* p = g_y4 + (size_t)n * 576 * 128 + oc;
    float s = 0.f;
#pragma unroll 4
    for (int i = 0; i < 576; i++) s += fmaxf(fmaf(p[i * 128], sc, sh), 0.f);
    g_f[n * 128 + oc] = s * (1.f / 576.f);
}

// ---------------- row-wise L2 normalize + split into bf16 hi/lo (K = 128) ----------------
__global__ void l2norm_split_k(const float* __restrict__ in,
                               __nv_bfloat16* __restrict__ oh,
                               __nv_bfloat16* __restrict__ ol, int rows) {
    int r = blockIdx.x * 8 + (threadIdx.x >> 5);
    if (r >= rows) return;
    int lane = threadIdx.x & 31;
    const float* p = in + (size_t)r * 128;
    float v0 = p[lane], v1 = p[lane + 32], v2 = p[lane + 64], v3 = p[lane + 96];
    float sq = v0 * v0 + v1 * v1 + v2 * v2 + v3 * v3;
#pragma unroll
    for (int o = 16; o > 0; o >>= 1) sq += __shfl_xor_sync(0xffffffffu, sq, o);
    float inv = 1.f / fmaxf(sqrtf(sq), 1e-12f);
    float v[4] = {v0 * inv, v1 * inv, v2 * inv, v3 * inv};
#pragma unroll
    for (int j = 0; j < 4; j++) {
        __nv_bfloat16 h = __float2bfloat16(v[j]);
        __nv_bfloat16 l = __float2bfloat16(v[j] - __bfloat162float(h));
        oh[(size_t)r * 128 + lane + 32 * j] = h;
        ol[(size_t)r * 128 + lane + 32 * j] = l;
    }
}

// ---------------- tensor-core bf16x3 GEMM: C = 64 * A(512x128) B(100000x128)^T ------------
__global__ __launch_bounds__(256) void sgemm_tc_k(
    const __nv_bfloat16* __restrict__ Ah, const __nv_bfloat16* __restrict__ Al,
    const __nv_bfloat16* __restrict__ Bh, const __nv_bfloat16* __restrict__ Bl,
    float* __restrict__ C) {
    extern __shared__ __nv_bfloat16 sm[];
    __nv_bfloat16* As_h = sm;             // [128][128]
    __nv_bfloat16* As_l = sm + 16384;
    __nv_bfloat16* Bs_h = sm + 32768;
    __nv_bfloat16* Bs_l = sm + 49152;
    const int tid = threadIdx.x;
    const int bm = blockIdx.y * 128;
    const int bn = blockIdx.x * 128;
    const int r = tid >> 1, half = tid & 1;

    {
        const uint4* sa_h = (const uint4*)(Ah + (size_t)(bm + r) * 128);
        const uint4* sa_l = (const uint4*)(Al + (size_t)(bm + r) * 128);
        uint4* da_h = (uint4*)As_h;
        uint4* da_l = (uint4*)As_l;
#pragma unroll
        for (int i = 0; i < 8; i++) {
            int c = half * 8 + i, cs = c ^ (r & 7);
            da_h[r * 16 + cs] = sa_h[c];
            da_l[r * 16 + cs] = sa_l[c];
        }
        int n = bn + r;
        bool v = (n < NCLS);
        const uint4* sb_h = (const uint4*)(Bh + (size_t)n * 128);
        const uint4* sb_l = (const uint4*)(Bl + (size_t)n * 128);
        uint4* db_h = (uint4*)Bs_h;
        uint4* db_l = (uint4*)Bs_l;
        uint4 z = make_uint4(0u, 0u, 0u, 0u);
#pragma unroll
        for (int i = 0; i < 8; i++) {
            int c = half * 8 + i, cs = c ^ (r & 7);
            db_h[r * 16 + cs] = v ? sb_h[c] : z;
            db_l[r * 16 + cs] = v ? sb_l[c] : z;
        }
    }
    __syncthreads();

    const int w = tid >> 5, lane = tid & 31;
    const int wm = w & 3, wn = w >> 2;

    float acc[2][8][4];
#pragma unroll
    for (int a = 0; a < 2; a++)
#pragma unroll
        for (int b = 0; b < 8; b++)
#pragma unroll
            for (int d = 0; d < 4; d++) acc[a][b][d] = 0.f;

    uint32_t ash = (uint32_t)__cvta_generic_to_shared(As_h);
    uint32_t asl = (uint32_t)__cvta_generic_to_shared(As_l);
    uint32_t bsh = (uint32_t)__cvta_generic_to_shared(Bs_h);
    uint32_t bsl = (uint32_t)__cvta_generic_to_shared(Bs_l);

#pragma unroll
    for (int kb = 0; kb < 8; kb++) {
        uint32_t ah[2][4], al[2][4];
#pragma unroll
        for (int mt = 0; mt < 2; mt++) {
            int ml = wm * 32 + mt * 16 + (lane & 15);
            int cs = (2 * kb + (lane >> 4)) ^ (ml & 7);
            uint32_t off = (uint32_t)(ml * 256 + cs * 16);
            ldsm4(ah[mt], ash + off);
            ldsm4(al[mt], asl + off);
        }
        uint32_t bh[8][2], bl[8][2];
#pragma unroll
        for (int np = 0; np < 4; np++) {
            int nl = wn * 64 + np * 16 + (lane & 7) + ((lane >> 4) << 3);
            int cs = (2 * kb + ((lane >> 3) & 1)) ^ (nl & 7);
            uint32_t off = (uint32_t)(nl * 256 + cs * 16);
            uint32_t t[4];
            ldsm4(t, bsh + off);
            bh[2 * np][0] = t[0]; bh[2 * np][1] = t[1];
            bh[2 * np + 1][0] = t[2]; bh[2 * np + 1][1] = t[3];
            ldsm4(t, bsl + off);
            bl[2 * np][0] = t[0]; bl[2 * np][1] = t[1];
            bl[2 * np + 1][0] = t[2]; bl[2 * np + 1][1] = t[3];
        }
#pragma unroll
        for (int mt = 0; mt < 2; mt++)
#pragma unroll
            for (int nt = 0; nt < 8; nt++) {
                mma_bf16(acc[mt][nt], ah[mt], bh[nt]);
                mma_bf16(acc[mt][nt], ah[mt], bl[nt]);
                mma_bf16(acc[mt][nt], al[mt], bh[nt]);
            }
    }

#pragma unroll
    for (int mt = 0; mt < 2; mt++) {
#pragma unroll
        for (int nt = 0; nt < 8; nt++) {
            int m = bm + wm * 32 + mt * 16 + (lane >> 2);
            int n = bn + wn * 64 + nt * 8 + ((lane & 3) << 1);
            if (n < NCLS) {
                float* cp0 = C + (size_t)m * NCLS + n;
                *(float2*)cp0 = make_float2(64.f * acc[mt][nt][0], 64.f * acc[mt][nt][1]);
                float* cp1 = C + (size_t)(m + 8) * NCLS + n;
                *(float2*)cp1 = make_float2(64.f * acc[mt][nt][2], 64.f * acc[mt][nt][3]);
            }
        }
    }
}

// ---------------- ArcFace margin fix-up ----------------
__global__ void margin_k(const int* __restrict__ gt, float* __restrict__ out) {
    int n = blockIdx.x * 256 + threadIdx.x;
    if (n >= NIMG) return;
    int c = gt[n];
    size_t idx = (size_t)n * NCLS + c;
    float v = out[idx] * (1.f / 64.f);
    float s = sqrtf(fmaxf(1.f - v * v, 0.f));
    const float cm = 0.87758256189037271612f;  // cos(0.5)
    const float sm = 0.47942553860420300027f;  // sin(0.5)
    out[idx] = 64.f * (v * cm - s * sm);
}

// ---------------- launch ----------------
extern "C" void kernel_launch(void* const* d_in, const int* in_sizes, int n_in,
                              void* d_out, int out_size) {
    const float* x  = (const float*)d_in[0];
    const int*   gt = (const int*)d_in[1];
    const float* w1 = (const float*)d_in[2];
    const float* g1 = (const float*)d_in[4];
    const float* be1 = (const float*)d_in[5];
    const float* w2 = (const float*)d_in[6];
    const float* g2 = (const float*)d_in[8];
    const float* be2 = (const float*)d_in[9];
    const float* w3 = (const float*)d_in[10];
    const float* g3 = (const float*)d_in[12];
    const float* be3 = (const float*)d_in[13];
    const float* w4 = (const float*)d_in[14];
    const float* g4 = (const float*)d_in[16];
    const float* be4 = (const float*)d_in[17];
    const float* aw = (const float*)d_in[18];
    float* out = (float*)d_out;

    // Resolve REAL device addresses of __device__ globals.
    float *p_y2, *p_y3, *p_y4, *p_f;
    __nv_bfloat16 *p_fh, *p_fl, *p_wh, *p_wl, *p_w4h, *p_w4l;
    float *p_s1, *p_q1, *p_sc1, *p_sh1;
    float *p_s2, *p_q2, *p_sc2, *p_sh2;
    float *p_s3, *p_q3, *p_sc3, *p_sh3;
    float *p_s4, *p_q4, *p_sc4, *p_sh4;
    cudaGetSymbolAddress((void**)&p_y2, g_y2);
    cudaGetSymbolAddress((void**)&p_y3, g_y3);
    cudaGetSymbolAddress((void**)&p_y4, g_y4);
    cudaGetSymbolAddress((void**)&p_f, g_f);
    cudaGetSymbolAddress((void**)&p_fh, g_fh);
    cudaGetSymbolAddress((void**)&p_fl, g_fl);
    cudaGetSymbolAddress((void**)&p_wh, g_wh);
    cudaGetSymbolAddress((void**)&p_wl, g_wl);
    cudaGetSymbolAddress((void**)&p_w4h, g_w4h);
    cudaGetSymbolAddress((void**)&p_w4l, g_w4l);
    cudaGetSymbolAddress((void**)&p_s1, g_s1);   cudaGetSymbolAddress((void**)&p_q1, g_q1);
    cudaGetSymbolAddress((void**)&p_sc1, g_sc1); cudaGetSymbolAddress((void**)&p_sh1, g_sh1);
    cudaGetSymbolAddress((void**)&p_s2, g_s2);   cudaGetSymbolAddress((void**)&p_q2, g_q2);
    cudaGetSymbolAddress((void**)&p_sc2, g_sc2); cudaGetSymbolAddress((void**)&p_sh2, g_sh2);
    cudaGetSymbolAddress((void**)&p_s3, g_s3);   cudaGetSymbolAddress((void**)&p_q3, g_q3);
    cudaGetSymbolAddress((void**)&p_sc3, g_sc3); cudaGetSymbolAddress((void**)&p_sh3, g_sh3);
    cudaGetSymbolAddress((void**)&p_s4, g_s4);   cudaGetSymbolAddress((void**)&p_q4, g_q4);
    cudaGetSymbolAddress((void**)&p_sc4, g_sc4); cudaGetSymbolAddress((void**)&p_sh4, g_sh4);

    cudaFuncSetAttribute(sgemm_tc_k, cudaFuncAttributeMaxDynamicSharedMemorySize, 131072);
    cudaFuncSetAttribute(conv4_tc_k, cudaFuncAttributeMaxDynamicSharedMemorySize, 98304);

    zero_stats_k<<<1, 128>>>();
    prep_w4_k<<<(4 * 9 * 128 * 16 + 255) / 256, 256>>>(w4, p_w4h, p_w4l);

    // layer 1: conv (+stats) -> scale
    conv1_k<<<dim3(512, 13), 256>>>(x, w1);
    scale_k<<<1, 16>>>(p_s1, p_q1, g1, be1, p_sc1, p_sh1, 16, 1.f / (512.f * 3136.f));

    // layer 2: conv (bn1 fused in, +stats) -> scale
    conv2_k<<<512, 416>>>(w2);
    scale_k<<<1, 32>>>(p_s2, p_q2, g2, be2, p_sc2, p_sh2, 32, 1.f / (512.f * 784.f));

    // layer 3: 32->64, 28->26 (fp32)
    conv3x3_k<32, 64, 28, 26, 352><<<dim3(512, 2), 352>>>(p_y2, w3, p_y3, p_sc2, p_sh2, p_s3, p_q3);
    scale_k<<<1, 64>>>(p_s3, p_q3, g3, be3, p_sc3, p_sh3, 64, 1.f / (512.f * 676.f));

    // layer 4: 64->128, 26->24 on tensor cores (bn3 fused in)
    conv4_tc_k<<<dim3(512, 3), 256, 98304>>>(p_y3, p_w4h, p_w4l, p_sc3, p_sh3, p_y4);
    stats4n_k<<<512, 128>>>();
    scale_k<<<1, 128>>>(p_s4, p_q4, g4, be4, p_sc4, p_sh4, 128, 1.f / (512.f * 576.f));

    // pool (bn4 fused) + normalize + bf16 hi/lo split
    gap_n_k<<<512, 128>>>();
    l2norm_split_k<<<64, 256>>>(p_f, p_fh, p_fl, 512);
    l2norm_split_k<<<(NCLS + 7) / 8, 256>>>(aw, p_wh, p_wl, NCLS);

    // cosine logits (x64) via bf16x3 tensor cores + margin
    sgemm_tc_k<<<dim3((NCLS + 127) / 128, 4), 256, 131072>>>(p_fh, p_fl, p_wh, p_wl, out);
    margin_k<<<2, 256>>>(gt, out);
}

// round 14
// speedup vs baseline: 3.5483x; 1.4362x over previous
#include <cuda_runtime.h>
#include <cuda_bf16.h>
#include <math.h>
#include <stdint.h>

#define NIMG 512
#define NCLS 100000

// ---------------- scratch (device globals; no allocation) ----------------
__device__ float g_y1[512 * 16 * 56 * 56];   // conv1 raw out [n][c][hw]
__device__ float g_y2[512 * 32 * 28 * 28];   // conv2 raw out [n][c][hw]
__device__ float g_y3[512 * 676 * 64];       // conv3 raw out [n][pix][oc]
__device__ float g_y4[512 * 576 * 128];      // conv4 raw out [n][pix][oc]
__device__ float g_f[512 * 128];
__device__ __nv_bfloat16 g_fh[512 * 128];
__device__ __nv_bfloat16 g_fl[512 * 128];
__device__ __nv_bfloat16 g_wh[NCLS * 128];
__device__ __nv_bfloat16 g_wl[NCLS * 128];
__device__ __nv_bfloat16 g_w4h[4 * 9 * 128 * 16];  // [chunk][tap][oc][icl]
__device__ __nv_bfloat16 g_w4l[4 * 9 * 128 * 16];
__device__ __nv_bfloat16 g_w3h[2 * 9 * 64 * 16];   // [chunk][tap][oc][icl]
__device__ __nv_bfloat16 g_w3l[2 * 9 * 64 * 16];
__device__ float g_s1[16], g_q1[16], g_sc1[16], g_sh1[16];
__device__ float g_s2[32], g_q2[32], g_sc2[32], g_sh2[32];
__device__ float g_s3[64], g_q3[64], g_sc3[64], g_sh3[64];
__device__ float g_s4[128], g_q4[128], g_sc4[128], g_sh4[128];

__global__ void zero_stats_k() {
    int t = threadIdx.x;
    if (t < 16)  { g_s1[t] = 0.f; g_q1[t] = 0.f; }
    if (t < 32)  { g_s2[t] = 0.f; g_q2[t] = 0.f; }
    if (t < 64)  { g_s3[t] = 0.f; g_q3[t] = 0.f; }
    if (t < 128) { g_s4[t] = 0.f; g_q4[t] = 0.f; }
}

// stats -> (scale, shift)
__global__ void scale_k(const float* __restrict__ s, const float* __restrict__ q,
                        const float* __restrict__ g, const float* __restrict__ be,
                        float* __restrict__ sc, float* __restrict__ sh, int C, float invCnt) {
    int c = threadIdx.x;
    if (c >= C) return;
    float mu = s[c] * invCnt;
    float var = fmaxf(q[c] * invCnt - mu * mu, 0.f);
    float a = g[c] * rsqrtf(var + 1e-5f);
    sc[c] = a;
    sh[c] = be[c] - mu * a;
}

// ---------------- conv1: 1->16, 4x4, s2, p1, 112 -> 56 (+fused stats) ----------------
__global__ __launch_bounds__(256) void conv1_k(const float* __restrict__ x,
                                               const float* __restrict__ w) {
    __shared__ float ws[256];  // [tap][oc]
    __shared__ float bs[16], bq[16];
    int tid = threadIdx.x;
    ws[(tid & 15) * 16 + (tid >> 4)] = w[tid];
    if (tid < 16) { bs[tid] = 0.f; bq[tid] = 0.f; }
    __syncthreads();
    int n = blockIdx.x;
    int p = blockIdx.y * 256 + tid;
    bool valid = (p < 3136);
    int pc = valid ? p : 3135;
    int oh = pc / 56, ow = pc % 56;
    const float* xin = x + (size_t)n * 112 * 112;
    float acc[16];
#pragma unroll
    for (int i = 0; i < 16; i++) acc[i] = 0.f;
#pragma unroll
    for (int kh = 0; kh < 4; kh++) {
        int ih = oh * 2 - 1 + kh;
        bool vh = ((unsigned)ih < 112u);
#pragma unroll
        for (int kw = 0; kw < 4; kw++) {
            int iw = ow * 2 - 1 + kw;
            float v = (vh && ((unsigned)iw < 112u)) ? xin[ih * 112 + iw] : 0.f;
            const float4* wp = (const float4*)(ws + (kh * 4 + kw) * 16);
#pragma unroll
            for (int q = 0; q < 4; q++) {
                float4 wv = wp[q];
                acc[4 * q + 0] += v * wv.x;
                acc[4 * q + 1] += v * wv.y;
                acc[4 * q + 2] += v * wv.z;
                acc[4 * q + 3] += v * wv.w;
            }
        }
    }
    float* out = g_y1 + (size_t)n * 16 * 3136;
    if (valid) {
#pragma unroll
        for (int oc = 0; oc < 16; oc++) out[oc * 3136 + p] = acc[oc];
    }
    int lane = tid & 31;
#pragma unroll
    for (int oc = 0; oc < 16; oc++) {
        float v = valid ? acc[oc] : 0.f;
        float q = v * v;
#pragma unroll
        for (int o = 16; o > 0; o >>= 1) {
            v += __shfl_xor_sync(0xffffffffu, v, o);
            q += __shfl_xor_sync(0xffffffffu, q, o);
        }
        if (lane == 0) { atomicAdd(&bs[oc], v); atomicAdd(&bq[oc], q); }
    }
    __syncthreads();
    if (tid < 16) { atomicAdd(&g_s1[tid], bs[tid]); atomicAdd(&g_q1[tid], bq[tid]); }
}

// ---------------- conv2: 16->32, 4x4, s2, p1, 56 -> 28 (bn1+relu fused in, stats out) --------
__global__ __launch_bounds__(416) void conv2_k(const float* __restrict__ w) {
    __shared__ float smi[2 * 58 * 58];
    __shared__ float smw[2 * 16 * 32];
    __shared__ float bs[32], bq[32];
    const int tid = threadIdx.x;
    const int n = blockIdx.x;

    for (int i = tid; i < 2 * 58 * 58; i += 416) smi[i] = 0.f;
    if (tid < 32) { bs[tid] = 0.f; bq[tid] = 0.f; }

    const int p0 = tid;
    const int p1 = tid + 416;
    const bool v1 = (p1 < 784);
    const int p1c = v1 ? p1 : 783;
    const int oh0 = p0 / 28, ow0 = p0 % 28;
    const int oh1 = p1c / 28, ow1 = p1c % 28;

    float acc0[32], acc1[32];
#pragma unroll
    for (int i = 0; i < 32; i++) { acc0[i] = 0.f; acc1[i] = 0.f; }

    const float* ain = g_y1 + (size_t)n * 16 * 3136;
    __syncthreads();

#pragma unroll 1
    for (int ic0 = 0; ic0 < 16; ic0 += 2) {
        float scA = g_sc1[ic0], shA = g_sh1[ic0];
        float scB = g_sc1[ic0 + 1], shB = g_sh1[ic0 + 1];
        for (int i = tid; i < 2 * 3136; i += 416) {
            int icl = i / 3136, r = i % 3136;
            int ih = r / 56, iw = r % 56;
            float raw = ain[(ic0 + icl) * 3136 + r];
            float sc = icl ? scB : scA, sh = icl ? shB : shA;
            smi[icl * 3364 + (ih + 1) * 58 + (iw + 1)] = fmaxf(fmaf(raw, sc, sh), 0.f);
        }
        for (int i = tid; i < 1024; i += 416) {
            int oc = i & 31, t = (i >> 5) & 15, icl = i >> 9;
            smw[i] = w[((oc * 16) + (ic0 + icl)) * 16 + t];
        }
        __syncthreads();
#pragma unroll 1
        for (int icl = 0; icl < 2; icl++) {
            const float* sip = smi + icl * 3364;
#pragma unroll
            for (int t = 0; t < 16; t++) {
                int kh = t >> 2, kw = t & 3;
                float in0 = sip[(oh0 * 2 + kh) * 58 + ow0 * 2 + kw];
                float in1 = sip[(oh1 * 2 + kh) * 58 + ow1 * 2 + kw];
                const float4* wp = (const float4*)(smw + ((icl * 16) + t) * 32);
#pragma unroll
                for (int q = 0; q < 8; q++) {
                    float4 wv = wp[q];
                    acc0[4 * q + 0] += in0 * wv.x; acc1[4 * q + 0] += in1 * wv.x;
                    acc0[4 * q + 1] += in0 * wv.y; acc1[4 * q + 1] += in1 * wv.y;
                    acc0[4 * q + 2] += in0 * wv.z; acc1[4 * q + 2] += in1 * wv.z;
                    acc0[4 * q + 3] += in0 * wv.w; acc1[4 * q + 3] += in1 * wv.w;
                }
            }
        }
        __syncthreads();
    }
    float* out = g_y2 + (size_t)n * 32 * 784;
#pragma unroll
    for (int oc = 0; oc < 32; oc++) {
        out[oc * 784 + p0] = acc0[oc];
        if (v1) out[oc * 784 + p1] = acc1[oc];
    }
    int lane = tid & 31;
#pragma unroll
    for (int oc = 0; oc < 32; oc++) {
        float v = acc0[oc] + (v1 ? acc1[oc] : 0.f);
        float q = acc0[oc] * acc0[oc] + (v1 ? acc1[oc] * acc1[oc] : 0.f);
#pragma unroll
        for (int o = 16; o > 0; o >>= 1) {
            v += __shfl_xor_sync(0xffffffffu, v, o);
            q += __shfl_xor_sync(0xffffffffu, q, o);
        }
        if (lane == 0) { atomicAdd(&bs[oc], v); atomicAdd(&bq[oc], q); }
    }
    __syncthreads();
    if (tid < 32) { atomicAdd(&g_s2[tid], bs[tid]); atomicAdd(&g_q2[tid], bq[tid]); }
}

// ---------------- weight prep: fp32 OIHW -> bf16 hi/lo [chunk][tap][oc][icl] ----------
__global__ void prep_w4_k(const float* __restrict__ w4,
                          __nv_bfloat16* __restrict__ Wh, __nv_bfloat16* __restrict__ Wl) {
    int i = blockIdx.x * 256 + threadIdx.x;
    if (i >= 4 * 9 * 128 * 16) return;
    int icl = i & 15;
    int oc = (i >> 4) & 127;
    int rest = i >> 11;       // chunk*9 + tap
    int t = rest % 9;
    int ch = rest / 9;
    float v = w4[((size_t)oc * 64 + ch * 16 + icl) * 9 + t];
    __nv_bfloat16 h = __float2bfloat16(v);
    Wh[i] = h;
    Wl[i] = __float2bfloat16(v - __bfloat162float(h));
}

__global__ void prep_w3_k(const float* __restrict__ w3,
                          __nv_bfloat16* __restrict__ Wh, __nv_bfloat16* __restrict__ Wl) {
    int i = blockIdx.x * 256 + threadIdx.x;
    if (i >= 2 * 9 * 64 * 16) return;
    int icl = i & 15;
    int oc = (i >> 4) & 63;
    int rest = i >> 10;       // chunk*9 + tap
    int t = rest % 9;
    int ch = rest / 9;
    float v = w3[((size_t)oc * 32 + ch * 16 + icl) * 9 + t];
    __nv_bfloat16 h = __float2bfloat16(v);
    Wh[i] = h;
    Wl[i] = __float2bfloat16(v - __bfloat162float(h));
}

// ---------------- mma helpers (proven) ----------------
__device__ __forceinline__ void ldsm4(uint32_t* r, uint32_t addr) {
    asm volatile("ldmatrix.sync.aligned.m8n8.x4.shared.b16 {%0,%1,%2,%3}, [%4];"
                 : "=r"(r[0]), "=r"(r[1]), "=r"(r[2]), "=r"(r[3]) : "r"(addr));
}
__device__ __forceinline__ void mma_bf16(float* c, const uint32_t* a, const uint32_t* b) {
    asm volatile(
        "mma.sync.aligned.m16n8k16.row.col.f32.bf16.bf16.f32 "
        "{%0,%1,%2,%3}, {%4,%5,%6,%7}, {%8,%9}, {%0,%1,%2,%3};"
        : "+f"(c[0]), "+f"(c[1]), "+f"(c[2]), "+f"(c[3])
        : "r"(a[0]), "r"(a[1]), "r"(a[2]), "r"(a[3]), "r"(b[0]), "r"(b[1]));
}

// ---------------- conv3 tensor-core shifted-GEMM (bf16x3), stats fused --------------
// grid (512 images, 4 m-tiles of 192 pixels). Input g_y2 [n][32][784] raw (bn2+relu fused).
// Output g_y3 [n][676][64] pixel-major. Stats accumulated into g_s3/g_q3.
__global__ __launch_bounds__(256) void conv3_tc_k(
    const float* __restrict__ act,
    const __nv_bfloat16* __restrict__ Wh, const __nv_bfloat16* __restrict__ Wl,
    const float* __restrict__ isc, const float* __restrict__ ish,
    float* __restrict__ out) {
    extern __shared__ char smraw[];
    __nv_bfloat16* S_h = (__nv_bfloat16*)smraw;                 // 308 rows x 32B
    __nv_bfloat16* S_l = (__nv_bfloat16*)(smraw + 10240);
    __nv_bfloat16* W_hs = (__nv_bfloat16*)(smraw + 20480);      // 9*64*32 = 18432
    __nv_bfloat16* W_ls = (__nv_bfloat16*)(smraw + 38912);
    float* Cs = (float*)smraw;                                  // epilogue reuse: 192*64*4
    float* bs = (float*)(smraw + 49152);
    float* bq = (float*)(smraw + 49408);

    const int tid = threadIdx.x;
    const int n = blockIdx.x;
    const int P0 = blockIdx.y * 192;
    const int row0 = P0 / 26;
    const int sbase = row0 * 28;
    const int slim = 784 - sbase;  // valid staged input pixels
    const int w = tid >> 5, lane = tid & 31;
    const int wm = w & 3, wn = w >> 2;  // 4 m-warps x 2 n-warps; warp tile 48m x 32n

    int abase[3];
#pragma unroll
    for (int mt = 0; mt < 3; mt++) {
        int p = P0 + wm * 48 + mt * 16 + (lane & 15);
        p = (p < 676) ? p : 675;
        abase[mt] = (p / 26) * 28 + (p % 26) - sbase;
    }

    float acc[3][4][4];
#pragma unroll
    for (int a = 0; a < 3; a++)
#pragma unroll
        for (int b = 0; b < 4; b++)
#pragma unroll
            for (int d = 0; d < 4; d++) acc[a][b][d] = 0.f;

    uint32_t sSh = (uint32_t)__cvta_generic_to_shared(S_h);
    uint32_t sSl = (uint32_t)__cvta_generic_to_shared(S_l);
    uint32_t sWh = (uint32_t)__cvta_generic_to_shared(W_hs);
    uint32_t sWl = (uint32_t)__cvta_generic_to_shared(W_ls);

#pragma unroll 1
    for (int ch = 0; ch < 2; ch++) {
        // stage S: 16 ICs x up-to-308 input pixels, bn2+relu, hi/lo split
#pragma unroll 1
        for (int icl = 0; icl < 16; icl++) {
            int c = ch * 16 + icl;
            const float* pl = act + ((size_t)n * 32 + c) * 784 + sbase;
            float sc = __ldg(&isc[c]), sh = __ldg(&ish[c]);
            int cidx = icl >> 3, e = icl & 7;
            for (int j = tid; j < 308; j += 256) {
                if (j < slim) {
                    float v = fmaxf(fmaf(pl[j], sc, sh), 0.f);
                    __nv_bfloat16 h = __float2bfloat16(v);
                    __nv_bfloat16 l = __float2bfloat16(v - __bfloat162float(h));
                    int off = j * 16 + (cidx ^ (j & 1)) * 8 + e;
                    S_h[off] = h;
                    S_l[off] = l;
                }
            }
        }
        // stage W chunk: 1152 uint4 each, row-parity swizzle
        {
            const uint4* srch = (const uint4*)(Wh + (size_t)ch * 9 * 64 * 16);
            const uint4* srcl = (const uint4*)(Wl + (size_t)ch * 9 * 64 * 16);
            uint4* dsth = (uint4*)W_hs;
            uint4* dstl = (uint4*)W_ls;
            for (int i = tid; i < 1152; i += 256) {
                int row = i >> 1, c = i & 1;
                int d = row * 2 + (c ^ (row & 1));
                dsth[d] = srch[i];
                dstl[d] = srcl[i];
            }
        }
        __syncthreads();

#pragma unroll 3
        for (int t = 0; t < 9; t++) {
            const int toff = (t / 3) * 28 + (t % 3);
            uint32_t ah[3][4], al[3][4];
#pragma unroll
            for (int mt = 0; mt < 3; mt++) {
                int row = abase[mt] + toff;
                uint32_t off = (uint32_t)(row * 32 + (((lane >> 4) ^ (row & 1)) * 16));
                ldsm4(ah[mt], sSh + off);
                ldsm4(al[mt], sSl + off);
            }
#pragma unroll
            for (int np = 0; np < 2; np++) {
                int nl = wn * 32 + np * 16 + (lane & 7) + ((lane >> 4) << 3);
                int cs = ((lane >> 3) & 1) ^ (nl & 1);
                uint32_t off = (uint32_t)((t * 64 + nl) * 32 + cs * 16);
                uint32_t th[4], tl[4];
                ldsm4(th, sWh + off);
                ldsm4(tl, sWl + off);
#pragma unroll
                for (int mt = 0; mt < 3; mt++) {
                    mma_bf16(acc[mt][2 * np], ah[mt], th);
                    mma_bf16(acc[mt][2 * np], ah[mt], tl);
                    mma_bf16(acc[mt][2 * np], al[mt], th);
                    mma_bf16(acc[mt][2 * np + 1], ah[mt], th + 2);
                    mma_bf16(acc[mt][2 * np + 1], ah[mt], tl + 2);
                    mma_bf16(acc[mt][2 * np + 1], al[mt], th + 2);
                }
            }
        }
        __syncthreads();
    }

    // ---- epilogue: acc -> Cs [192][64] swizzled -> coalesced stores + fused stats ----
#pragma unroll
    for (int mt = 0; mt < 3; mt++) {
#pragma unroll
        for (int nt = 0; nt < 4; nt++) {
            int r0 = wm * 48 + mt * 16 + (lane >> 2);
            int c0 = wn * 32 + nt * 8 + ((lane & 3) << 1);
            int ph0 = ((c0 >> 2) ^ (r0 & 7));
            *(float2*)&Cs[r0 * 64 + ph0 * 4 + (c0 & 3)] = make_float2(acc[mt][nt][0], acc[mt][nt][1]);
            int r1 = r0 + 8;
            int ph1 = ((c0 >> 2) ^ (r1 & 7));
            *(float2*)&Cs[r1 * 64 + ph1 * 4 + (c0 & 3)] = make_float2(acc[mt][nt][2], acc[mt][nt][3]);
        }
    }
    __syncthreads();
    if (tid < 64) { bs[tid] = 0.f; bq[tid] = 0.f; }
    __syncthreads();
    const int vp = min(676 - P0, 192);
    uint4* og = (uint4*)(out + (size_t)n * 676 * 64);
    const uint4* Cs4 = (const uint4*)Cs;
    const int cc = tid & 15;
    float ls0 = 0.f, ls1 = 0.f, ls2 = 0.f, ls3 = 0.f;
    float lq0 = 0.f, lq1 = 0.f, lq2 = 0.f, lq3 = 0.f;
    for (int i = tid; i < vp * 16; i += 256) {
        int p = i >> 4;
        uint4 v = Cs4[p * 16 + (cc ^ (p & 7))];
        og[(size_t)(P0 + p) * 16 + cc] = v;
        float f0 = __uint_as_float(v.x), f1 = __uint_as_float(v.y);
        float f2 = __uint_as_float(v.z), f3 = __uint_as_float(v.w);
        ls0 += f0; lq0 += f0 * f0;
        ls1 += f1; lq1 += f1 * f1;
        ls2 += f2; lq2 += f2 * f2;
        ls3 += f3; lq3 += f3 * f3;
    }
    atomicAdd(&bs[cc * 4 + 0], ls0); atomicAdd(&bq[cc * 4 + 0], lq0);
    atomicAdd(&bs[cc * 4 + 1], ls1); atomicAdd(&bq[cc * 4 + 1], lq1);
    atomicAdd(&bs[cc * 4 + 2], ls2); atomicAdd(&bq[cc * 4 + 2], lq2);
    atomicAdd(&bs[cc * 4 + 3], ls3); atomicAdd(&bq[cc * 4 + 3], lq3);
    __syncthreads();
    if (tid < 64) { atomicAdd(&g_s3[tid], bs[tid]); atomicAdd(&g_q3[tid], bq[tid]); }
}

// ---------------- conv4 tensor-core shifted-GEMM (bf16x3), stats fused --------------
// Input g_y3 [n][676][64] pixel-major (bn3+relu fused in staging).
__global__ __launch_bounds__(256) void conv4_tc_k(
    const float* __restrict__ act,
    const __nv_bfloat16* __restrict__ Wh, const __nv_bfloat16* __restrict__ Wl,
    const float* __restrict__ isc, const float* __restrict__ ish,
    float* __restrict__ out) {
    extern __shared__ char smraw[];
    __nv_bfloat16* S_h = (__nv_bfloat16*)smraw;                  // 260 rows x 32B -> 8448
    __nv_bfloat16* S_l = (__nv_bfloat16*)(smraw + 8448);
    __nv_bfloat16* W_hs = (__nv_bfloat16*)(smraw + 16896);       // 9*128*32 = 36864
    __nv_bfloat16* W_ls = (__nv_bfloat16*)(smraw + 16896 + 36864);
    float* Cs = (float*)smraw;                                   // 192*128*4 = 98304
    float* bs = (float*)(smraw + 98304);
    float* bq = (float*)(smraw + 98816);

    const int tid = threadIdx.x;
    const int n = blockIdx.x;
    const int mt3 = blockIdx.y;   // 0..2
    const int oh0 = mt3 * 8;
    const int w = tid >> 5, lane = tid & 31;
    const int wm = w & 3, wn = w >> 2;  // warp tile 48m x 64n

    int abase[3];
#pragma unroll
    for (int mt = 0; mt < 3; mt++) {
        int p = wm * 48 + mt * 16 + (lane & 15);
        abase[mt] = (p / 24) * 26 + (p % 24);
    }

    float acc[3][8][4];
#pragma unroll
    for (int a = 0; a < 3; a++)
#pragma unroll
        for (int b = 0; b < 8; b++)
#pragma unroll
            for (int d = 0; d < 4; d++) acc[a][b][d] = 0.f;

    uint32_t sSh = (uint32_t)__cvta_generic_to_shared(S_h);
    uint32_t sSl = (uint32_t)__cvta_generic_to_shared(S_l);
    uint32_t sWh = (uint32_t)__cvta_generic_to_shared(W_hs);
    uint32_t sWl = (uint32_t)__cvta_generic_to_shared(W_ls);

#pragma unroll 1
    for (int ch = 0; ch < 4; ch++) {
        // ---- stage S from pixel-major act: 260 pixels x 16 ICs, float4 loads ----
        {
            const float4* a4 = (const float4*)(act + ((size_t)n * 676 + oh0 * 26) * 64 + ch * 16);
            // a4 stride per pixel = 16 float4s
            for (int i = tid; i < 1040; i += 256) {
                int j = i >> 2, g = i & 3;
                float4 v4 = a4[(size_t)j * 16 + g];
                float4 scv = *(const float4*)(isc + ch * 16 + g * 4);
                float4 shv = *(const float4*)(ish + ch * 16 + g * 4);
                float e0 = fmaxf(fmaf(v4.x, scv.x, shv.x), 0.f);
                float e1 = fmaxf(fmaf(v4.y, scv.y, shv.y), 0.f);
                float e2 = fmaxf(fmaf(v4.z, scv.z, shv.z), 0.f);
                float e3 = fmaxf(fmaf(v4.w, scv.w, shv.w), 0.f);
                int cidx = g >> 1;
                int off = j * 16 + (cidx ^ (j & 1)) * 8 + (g & 1) * 4;
                __nv_bfloat16 h0 = __float2bfloat16(e0);
                __nv_bfloat16 h1 = __float2bfloat16(e1);
                __nv_bfloat16 h2 = __float2bfloat16(e2);
                __nv_bfloat16 h3 = __float2bfloat16(e3);
                S_h[off + 0] = h0; S_h[off + 1] = h1; S_h[off + 2] = h2; S_h[off + 3] = h3;
                S_l[off + 0] = __float2bfloat16(e0 - __bfloat162float(h0));
                S_l[off + 1] = __float2bfloat16(e1 - __bfloat162float(h1));
                S_l[off + 2] = __float2bfloat16(e2 - __bfloat162float(h2));
                S_l[off + 3] = __float2bfloat16(e3 - __bfloat162float(h3));
            }
        }
        // ---- stage W chunk ----
        {
            const uint4* srch = (const uint4*)(Wh + (size_t)ch * 9 * 128 * 16);
            const uint4* srcl = (const uint4*)(Wl + (size_t)ch * 9 * 128 * 16);
            uint4* dsth = (uint4*)W_hs;
            uint4* dstl = (uint4*)W_ls;
            for (int i = tid; i < 2304; i += 256) {
                int row = i >> 1, c = i & 1;
                int d = row * 2 + (c ^ (row & 1));
                dsth[d] = srch[i];
                dstl[d] = srcl[i];
            }
        }
        __syncthreads();

#pragma unroll 3
        for (int t = 0; t < 9; t++) {
            const int toff = (t / 3) * 26 + (t % 3);
            uint32_t ah[3][4], al[3][4];
#pragma unroll
            for (int mt = 0; mt < 3; mt++) {
                int row = abase[mt] + toff;
                uint32_t off = (uint32_t)(row * 32 + (((lane >> 4) ^ (row & 1)) * 16));
                ldsm4(ah[mt], sSh + off);
                ldsm4(al[mt], sSl + off);
            }
#pragma unroll
            for (int np = 0; np < 4; np++) {
                int nl = wn * 64 + np * 16 + (lane & 7) + ((lane >> 4) << 3);
                int cs = ((lane >> 3) & 1) ^ (nl & 1);
                uint32_t off = (uint32_t)((t * 128 + nl) * 32 + cs * 16);
                uint32_t th[4], tl[4];
                ldsm4(th, sWh + off);
                ldsm4(tl, sWl + off);
#pragma unroll
                for (int mt = 0; mt < 3; mt++) {
                    mma_bf16(acc[mt][2 * np], ah[mt], th);
                    mma_bf16(acc[mt][2 * np], ah[mt], tl);
                    mma_bf16(acc[mt][2 * np], al[mt], th);
                    mma_bf16(acc[mt][2 * np + 1], ah[mt], th + 2);
                    mma_bf16(acc[mt][2 * np + 1], ah[mt], tl + 2);
                    mma_bf16(acc[mt][2 * np + 1], al[mt], th + 2);
                }
            }
        }
        __syncthreads();
    }

    // ---- epilogue: Cs [192][128] swizzled -> coalesced stores + fused stats ----
#pragma unroll
    for (int mt = 0; mt < 3; mt++) {
#pragma unroll
        for (int nt = 0; nt < 8; nt++) {
            int r0 = wm * 48 + mt * 16 + (lane >> 2);
            int c0 = wn * 64 + nt * 8 + ((lane & 3) << 1);
            int ph0 = ((c0 >> 2) ^ (r0 & 7));
            *(float2*)&Cs[r0 * 128 + ph0 * 4 + (c0 & 3)] = make_float2(acc[mt][nt][0], acc[mt][nt][1]);
            int r1 = r0 + 8;
            int ph1 = ((c0 >> 2) ^ (r1 & 7));
            *(float2*)&Cs[r1 * 128 + ph1 * 4 + (c0 & 3)] = make_float2(acc[mt][nt][2], acc[mt][nt][3]);
        }
    }
    __syncthreads();
    if (tid < 128) { bs[tid] = 0.f; bq[tid] = 0.f; }
    __syncthreads();
    uint4* og = (uint4*)(out + ((size_t)n * 576 + mt3 * 192) * 128);
    const uint4* Cs4 = (const uint4*)Cs;
    const int cc = tid & 31;
    float ls0 = 0.f, ls1 = 0.f, ls2 = 0.f, ls3 = 0.f;
    float lq0 = 0.f, lq1 = 0.f, lq2 = 0.f, lq3 = 0.f;
    for (int i = tid; i < 6144; i += 256) {
        int p = i >> 5;
        uint4 v = Cs4[p * 32 + (cc ^ (p & 7))];
        og[i] = v;
        float f0 = __uint_as_float(v.x), f1 = __uint_as_float(v.y);
        float f2 = __uint_as_float(v.z), f3 = __uint_as_float(v.w);
        ls0 += f0; lq0 += f0 * f0;
        ls1 += f1; lq1 += f1 * f1;
        ls2 += f2; lq2 += f2 * f2;
        ls3 += f3; lq3 += f3 * f3;
    }
    atomicAdd(&bs[cc * 4 + 0], ls0); atomicAdd(&bq[cc * 4 + 0], lq0);
    atomicAdd(&bs[cc * 4 + 1], ls1); atomicAdd(&bq[cc * 4 + 1], lq1);
    atomicAdd(&bs[cc * 4 + 2], ls2); atomicAdd(&bq[cc * 4 + 2], lq2);
    atomicAdd(&bs[cc * 4 + 3], ls3); atomicAdd(&bq[cc * 4 + 3], lq3);
    __syncthreads();
    if (tid < 128) { atomicAdd(&g_s4[tid], bs[tid]); atomicAdd(&g_q4[tid], bq[tid]); }
}

// ---------------- GAP with bn4+relu fused (layout [n][pix][oc]) ----------------
__global__ void gap_n_k() {
    int n = blockIdx.x;
    int oc = threadIdx.x;
    float sc = g_sc4[oc], sh = g_sh4[oc];
    const float* p = g_y4 + (size_t)n * 576 * 128 + oc;
    float s = 0.f;
#pragma unroll 4
    for (int i = 0; i < 576; i++) s += fmaxf(fmaf(p[i * 128], sc, sh), 0.f);
    g_f[n * 128 + oc] = s * (1.f / 576.f);
}

// ---------------- row-wise L2 normalize + split into bf16 hi/lo (K = 128) ----------------
__global__ void l2norm_split_k(const float* __restrict__ in,
                               __nv_bfloat16* __restrict__ oh,
                               __nv_bfloat16* __restrict__ ol, int rows) {
    int r = blockIdx.x * 8 + (threadIdx.x >> 5);
    if (r >= rows) return;
    int lane = threadIdx.x & 31;
    const float* p = in + (size_t)r * 128;
    float v0 = p[lane], v1 = p[lane + 32], v2 = p[lane + 64], v3 = p[lane + 96];
    float sq = v0 * v0 + v1 * v1 + v2 * v2 + v3 * v3;
#pragma unroll
    for (int o = 16; o > 0; o >>= 1) sq += __shfl_xor_sync(0xffffffffu, sq, o);
    float inv = 1.f / fmaxf(sqrtf(sq), 1e-12f);
    float v[4] = {v0 * inv, v1 * inv, v2 * inv, v3 * inv};
#pragma unroll
    for (int j = 0; j < 4; j++) {
        __nv_bfloat16 h = __float2bfloat16(v[j]);
        __nv_bfloat16 l = __float2bfloat16(v[j] - __bfloat162float(h));
        oh[(size_t)r * 128 + lane + 32 * j] = h;
        ol[(size_t)r * 128 + lane + 32 * j] = l;
    }
}

// ---------------- tensor-core bf16x3 GEMM: C = 64 * A(512x128) B(100000x128)^T ------------
__global__ __launch_bounds__(256) void sgemm_tc_k(
    const __nv_bfloat16* __restrict__ Ah, const __nv_bfloat16* __restrict__ Al,
    const __nv_bfloat16* __restrict__ Bh, const __nv_bfloat16* __restrict__ Bl,
    float* __restrict__ C) {
    extern __shared__ __nv_bfloat16 sm[];
    __nv_bfloat16* As_h = sm;             // [128][128]
    __nv_bfloat16* As_l = sm + 16384;
    __nv_bfloat16* Bs_h = sm + 32768;
    __nv_bfloat16* Bs_l = sm + 49152;
    const int tid = threadIdx.x;
    const int bm = blockIdx.y * 128;
    const int bn = blockIdx.x * 128;
    const int r = tid >> 1, half = tid & 1;

    {
        const uint4* sa_h = (const uint4*)(Ah + (size_t)(bm + r) * 128);
        const uint4* sa_l = (const uint4*)(Al + (size_t)(bm + r) * 128);
        uint4* da_h = (uint4*)As_h;
        uint4* da_l = (uint4*)As_l;
#pragma unroll
        for (int i = 0; i < 8; i++) {
            int c = half * 8 + i, cs = c ^ (r & 7);
            da_h[r * 16 + cs] = sa_h[c];
            da_l[r * 16 + cs] = sa_l[c];
        }
        int n = bn + r;
        bool v = (n < NCLS);
        const uint4* sb_h = (const uint4*)(Bh + (size_t)n * 128);
        const uint4* sb_l = (const uint4*)(Bl + (size_t)n * 128);
        uint4* db_h = (uint4*)Bs_h;
        uint4* db_l = (uint4*)Bs_l;
        uint4 z = make_uint4(0u, 0u, 0u, 0u);
#pragma unroll
        for (int i = 0; i < 8; i++) {
            int c = half * 8 + i, cs = c ^ (r & 7);
            db_h[r * 16 + cs] = v ? sb_h[c] : z;
            db_l[r * 16 + cs] = v ? sb_l[c] : z;
        }
    }
    __syncthreads();

    const int w = tid >> 5, lane = tid & 31;
    const int wm = w & 3, wn = w >> 2;

    float acc[2][8][4];
#pragma unroll
    for (int a = 0; a < 2; a++)
#pragma unroll
        for (int b = 0; b < 8; b++)
#pragma unroll
            for (int d = 0; d < 4; d++) acc[a][b][d] = 0.f;

    uint32_t ash = (uint32_t)__cvta_generic_to_shared(As_h);
    uint32_t asl = (uint32_t)__cvta_generic_to_shared(As_l);
    uint32_t bsh = (uint32_t)__cvta_generic_to_shared(Bs_h);
    uint32_t bsl = (uint32_t)__cvta_generic_to_shared(Bs_l);

#pragma unroll
    for (int kb = 0; kb < 8; kb++) {
        uint32_t ah[2][4], al[2][4];
#pragma unroll
        for (int mt = 0; mt < 2; mt++) {
            int ml = wm * 32 + mt * 16 + (lane & 15);
            int cs = (2 * kb + (lane >> 4)) ^ (ml & 7);
            uint32_t off = (uint32_t)(ml * 256 + cs * 16);
            ldsm4(ah[mt], ash + off);
            ldsm4(al[mt], asl + off);
        }
        uint32_t bh[8][2], bl[8][2];
#pragma unroll
        for (int np = 0; np < 4; np++) {
            int nl = wn * 64 + np * 16 + (lane & 7) + ((lane >> 4) << 3);
            int cs = (2 * kb + ((lane >> 3) & 1)) ^ (nl & 7);
            uint32_t off = (uint32_t)(nl * 256 + cs * 16);
            uint32_t t[4];
            ldsm4(t, bsh + off);
            bh[2 * np][0] = t[0]; bh[2 * np][1] = t[1];
            bh[2 * np + 1][0] = t[2]; bh[2 * np + 1][1] = t[3];
            ldsm4(t, bsl + off);
            bl[2 * np][0] = t[0]; bl[2 * np][1] = t[1];
            bl[2 * np + 1][0] = t[2]; bl[2 * np + 1][1] = t[3];
        }
#pragma unroll
        for (int mt = 0; mt < 2; mt++)
#pragma unroll
            for (int nt = 0; nt < 8; nt++) {
                mma_bf16(acc[mt][nt], ah[mt], bh[nt]);
                mma_bf16(acc[mt][nt], ah[mt], bl[nt]);
                mma_bf16(acc[mt][nt], al[mt], bh[nt]);
            }
    }

#pragma unroll
    for (int mt = 0; mt < 2; mt++) {
#pragma unroll
        for (int nt = 0; nt < 8; nt++) {
            int m = bm + wm * 32 + mt * 16 + (lane >> 2);
            int n = bn + wn * 64 + nt * 8 + ((lane & 3) << 1);
            if (n < NCLS) {
                float* cp0 = C + (size_t)m * NCLS + n;
                *(float2*)cp0 = make_float2(64.f * acc[mt][nt][0], 64.f * acc[mt][nt][1]);
                float* cp1 = C + (size_t)(m + 8) * NCLS + n;
                *(float2*)cp1 = make_float2(64.f * acc[mt][nt][2], 64.f * acc[mt][nt][3]);
            }
        }
    }
}

// ---------------- ArcFace margin fix-up ----------------
__global__ void margin_k(const int* __restrict__ gt, float* __restrict__ out) {
    int n = blockIdx.x * 256 + threadIdx.x;
    if (n >= NIMG) return;
    int c = gt[n];
    size_t idx = (size_t)n * NCLS + c;
    float v = out[idx] * (1.f / 64.f);
    float s = sqrtf(fmaxf(1.f - v * v, 0.f));
    const float cm = 0.87758256189037271612f;  // cos(0.5)
    const float sm = 0.47942553860420300027f;  // sin(0.5)
    out[idx] = 64.f * (v * cm - s * sm);
}

// ---------------- launch ----------------
extern "C" void kernel_launch(void* const* d_in, const int* in_sizes, int n_in,
                              void* d_out, int out_size) {
    const float* x  = (const float*)d_in[0];
    const int*   gt = (const int*)d_in[1];
    const float* w1 = (const float*)d_in[2];
    const float* g1 = (const float*)d_in[4];
    const float* be1 = (const float*)d_in[5];
    const float* w2 = (const float*)d_in[6];
    const float* g2 = (const float*)d_in[8];
    const float* be2 = (const float*)d_in[9];
    const float* w3 = (const float*)d_in[10];
    const float* g3 = (const float*)d_in[12];
    const float* be3 = (const float*)d_in[13];
    const float* w4 = (const float*)d_in[14];
    const float* g4 = (const float*)d_in[16];
    const float* be4 = (const float*)d_in[17];
    const float* aw = (const float*)d_in[18];
    float* out = (float*)d_out;

    // Resolve REAL device addresses of __device__ globals.
    float *p_y2, *p_y3, *p_y4, *p_f;
    __nv_bfloat16 *p_fh, *p_fl, *p_wh, *p_wl, *p_w4h, *p_w4l, *p_w3h, *p_w3l;
    float *p_s1, *p_q1, *p_sc1, *p_sh1;
    float *p_s2, *p_q2, *p_sc2, *p_sh2;
    float *p_s3, *p_q3, *p_sc3, *p_sh3;
    float *p_s4, *p_q4, *p_sc4, *p_sh4;
    cudaGetSymbolAddress((void**)&p_y2, g_y2);
    cudaGetSymbolAddress((void**)&p_y3, g_y3);
    cudaGetSymbolAddress((void**)&p_y4, g_y4);
    cudaGetSymbolAddress((void**)&p_f, g_f);
    cudaGetSymbolAddress((void**)&p_fh, g_fh);
    cudaGetSymbolAddress((void**)&p_fl, g_fl);
    cudaGetSymbolAddress((void**)&p_wh, g_wh);
    cudaGetSymbolAddress((void**)&p_wl, g_wl);
    cudaGetSymbolAddress((void**)&p_w4h, g_w4h);
    cudaGetSymbolAddress((void**)&p_w4l, g_w4l);
    cudaGetSymbolAddress((void**)&p_w3h, g_w3h);
    cudaGetSymbolAddress((void**)&p_w3l, g_w3l);
    cudaGetSymbolAddress((void**)&p_s1, g_s1);   cudaGetSymbolAddress((void**)&p_q1, g_q1);
    cudaGetSymbolAddress((void**)&p_sc1, g_sc1); cudaGetSymbolAddress((void**)&p_sh1, g_sh1);
    cudaGetSymbolAddress((void**)&p_s2, g_s2);   cudaGetSymbolAddress((void**)&p_q2, g_q2);
    cudaGetSymbolAddress((void**)&p_sc2, g_sc2); cudaGetSymbolAddress((void**)&p_sh2, g_sh2);
    cudaGetSymbolAddress((void**)&p_s3, g_s3);   cudaGetSymbolAddress((void**)&p_q3, g_q3);
    cudaGetSymbolAddress((void**)&p_sc3, g_sc3); cudaGetSymbolAddress((void**)&p_sh3, g_sh3);
    cudaGetSymbolAddress((void**)&p_s4, g_s4);   cudaGetSymbolAddress((void**)&p_q4, g_q4);
    cudaGetSymbolAddress((void**)&p_sc4, g_sc4); cudaGetSymbolAddress((void**)&p_sh4, g_sh4);

    cudaFuncSetAttribute(sgemm_tc_k, cudaFuncAttributeMaxDynamicSharedMemorySize, 131072);
    cudaFuncSetAttribute(conv4_tc_k, cudaFuncAttributeMaxDynamicSharedMemorySize, 99328);
    cudaFuncSetAttribute(conv3_tc_k, cudaFuncAttributeMaxDynamicSharedMemorySize, 57344);

    zero_stats_k<<<1, 128>>>();
    prep_w4_k<<<(4 * 9 * 128 * 16 + 255) / 256, 256>>>(w4, p_w4h, p_w4l);
    prep_w3_k<<<(2 * 9 * 64 * 16 + 255) / 256, 256>>>(w3, p_w3h, p_w3l);

    // layer 1: conv (+stats) -> scale
    conv1_k<<<dim3(512, 13), 256>>>(x, w1);
    scale_k<<<1, 16>>>(p_s1, p_q1, g1, be1, p_sc1, p_sh1, 16, 1.f / (512.f * 3136.f));

    // layer 2: conv (bn1 fused in, +stats) -> scale
    conv2_k<<<512, 416>>>(w2);
    scale_k<<<1, 32>>>(p_s2, p_q2, g2, be2, p_sc2, p_sh2, 32, 1.f / (512.f * 784.f));

    // layer 3: 32->64, 28->26 on tensor cores (bn2 fused in, stats fused out)
    conv3_tc_k<<<dim3(512, 4), 256, 57344>>>(p_y2, p_w3h, p_w3l, p_sc2, p_sh2, p_y3);
    scale_k<<<1, 64>>>(p_s3, p_q3, g3, be3, p_sc3, p_sh3, 64, 1.f / (512.f * 676.f));

    // layer 4: 64->128, 26->24 on tensor cores (bn3 fused in, stats fused out)
    conv4_tc_k<<<dim3(512, 3), 256, 99328>>>(p_y3, p_w4h, p_w4l, p_sc3, p_sh3, p_y4);
    scale_k<<<1, 128>>>(p_s4, p_q4, g4, be4, p_sc4, p_sh4, 128, 1.f / (512.f * 576.f));

    // pool (bn4 fused) + normalize + bf16 hi/lo split
    gap_n_k<<<512, 128>>>();
    l2norm_split_k<<<64, 256>>>(p_f, p_fh, p_fl, 512);
    l2norm_split_k<<<(NCLS + 7) / 8, 256>>>(aw, p_wh, p_wl, NCLS);

    // cosine logits (x64) via bf16x3 tensor cores + margin
    sgemm_tc_k<<<dim3((NCLS + 127) / 128, 4), 256, 131072>>>(p_fh, p_fl, p_wh, p_wl, out);
    margin_k<<<2, 256>>>(gt, out);
}